// round 13
// baseline (speedup 1.0000x reference)
#include <cuda_runtime.h>
#include <cuda_bf16.h>
#include <math.h>
#include <stdint.h>
#include <stddef.h>

// Problem dims
#define Bsz 256
#define Ssz 512
#define Fdim 128
#define Hdim 128
#define G3  384   // 3*H

// Output layout (tuple flattened): h_enc, output, z, gamma, dis, dis_perm
#define OFF_HENC  ((size_t)0)
#define OFF_OUT   ((size_t)32768)                       // 256*128
#define OFF_Z     ((size_t)(32768 + 16777216))          // + 256*512*128
#define OFF_GAMMA ((size_t)(OFF_Z + 256*129))
#define OFF_DIS   ((size_t)(OFF_GAMMA + 256*4))
#define OFF_DISP  ((size_t)(OFF_DIS + 256*8*128))

typedef unsigned long long ull;

// Scratch (device globals; no allocations allowed)
__device__ float g_Genc[(size_t)Ssz * Bsz * G3];    // [t][b][g]  192 MB
__device__ float g_Hdec[(size_t)Ssz * Bsz * Hdim];  // [i][b][j]   64 MB
__device__ float g_Henc[Bsz * Hdim];
__device__ float g_Mf[G3 * Hdim];
__device__ float g_bf[G3];
__device__ int   g_perm[8 * Bsz];
// bf16 split operands. g_Xh/g_Xl are REUSED: X split for gi GEMM, then Hdec
// split for the out GEMM (identical element counts).
__device__ __nv_bfloat16 g_Xh[(size_t)131072 * 128];   // 33.5 MB
__device__ __nv_bfloat16 g_Xl[(size_t)131072 * 128];
__device__ __nv_bfloat16 g_Wh[G3 * 128];
__device__ __nv_bfloat16 g_Wl[G3 * 128];
__device__ __nv_bfloat16 g_Oh[128 * 128];              // out_W split
__device__ __nv_bfloat16 g_Ol[128 * 128];

__device__ __forceinline__ float sigf(float x) { return 1.0f / (1.0f + expf(-x)); }

// ---- packed f32x2 helpers (used by dec only) ----
__device__ __forceinline__ ull pk2(float lo, float hi) {
    ull r; asm("mov.b64 %0, {%1, %2};" : "=l"(r) : "f"(lo), "f"(hi)); return r;
}
__device__ __forceinline__ ull f2fma(ull a, ull b, ull c) {
    ull d; asm("fma.rn.f32x2 %0, %1, %2, %3;" : "=l"(d) : "l"(a), "l"(b), "l"(c)); return d;
}
__device__ __forceinline__ float psum(ull v) {
    float a, b; asm("mov.b64 {%0, %1}, %2;" : "=f"(a), "=f"(b) : "l"(v)); return a + b;
}

__device__ __forceinline__ unsigned smaddr(const void* p) {
    unsigned a;
    asm("{ .reg .u64 t; cvta.to.shared.u64 t, %1; cvt.u32.u64 %0, t; }" : "=r"(a) : "l"(p));
    return a;
}

__device__ __forceinline__ void ldsm4(unsigned* f, unsigned addr) {
    asm volatile("ldmatrix.sync.aligned.m8n8.x4.shared.b16 {%0,%1,%2,%3}, [%4];"
                 : "=r"(f[0]), "=r"(f[1]), "=r"(f[2]), "=r"(f[3]) : "r"(addr));
}
__device__ __forceinline__ void mma16816(float* d, const unsigned* a, unsigned b0, unsigned b1) {
    asm volatile(
        "mma.sync.aligned.m16n8k16.row.col.f32.bf16.bf16.f32 "
        "{%0,%1,%2,%3}, {%4,%5,%6,%7}, {%8,%9}, {%0,%1,%2,%3};"
        : "+f"(d[0]), "+f"(d[1]), "+f"(d[2]), "+f"(d[3])
        : "r"(a[0]), "r"(a[1]), "r"(a[2]), "r"(a[3]), "r"(b0), "r"(b1));
}

// ---------------------------------------------------------------------------
// Threefry2x32 (exact JAX constants)
// ---------------------------------------------------------------------------
__device__ __forceinline__ uint2 threefry(unsigned k0, unsigned k1,
                                          unsigned x0, unsigned x1) {
    unsigned ks2 = k0 ^ k1 ^ 0x1BD11BDAu;
    x0 += k0; x1 += k1;
#define TFR(r) { x0 += x1; x1 = (x1 << (r)) | (x1 >> (32 - (r))); x1 ^= x0; }
    TFR(13) TFR(15) TFR(26) TFR(6)   x0 += k1;  x1 += ks2 + 1u;
    TFR(17) TFR(29) TFR(16) TFR(24)  x0 += ks2; x1 += k0 + 2u;
    TFR(13) TFR(15) TFR(26) TFR(6)   x0 += k0;  x1 += k1 + 3u;
    TFR(17) TFR(29) TFR(16) TFR(24)  x0 += k1;  x1 += ks2 + 4u;
    TFR(13) TFR(15) TFR(26) TFR(6)   x0 += ks2; x1 += k0 + 5u;
#undef TFR
    return make_uint2(x0, x1);
}

__global__ void perm_kernel(int* __restrict__ perm) {
    __shared__ unsigned sk[8][2];
    __shared__ unsigned bits[256];
    int t = threadIdx.x;
    if (t < 8) {
        uint2 pk = threefry(0u, 42u, 0u, (unsigned)t);
        uint2 s  = threefry(pk.x, pk.y, 0u, 1u);
        sk[t][0] = s.x; sk[t][1] = s.y;
    }
    __syncthreads();
    for (int k = 0; k < 8; k++) {
        uint2 y = threefry(sk[k][0], sk[k][1], 0u, (unsigned)t);
        bits[t] = y.x ^ y.y;
        __syncthreads();
        unsigned mine = bits[t];
        int rank = 0;
        for (int j = 0; j < 256; j++) {
            unsigned o = bits[j];
            rank += (o < mine) || (o == mine && j < t);
        }
        perm[k * 256 + rank] = t;
        __syncthreads();
    }
}

// ---------------------------------------------------------------------------
// bf16 split conversions
// ---------------------------------------------------------------------------
__global__ void conv_x(const float* __restrict__ X) {
    unsigned c = blockIdx.x * blockDim.x + threadIdx.x;
    int k0 = (c & 15) * 8;
    int t = (int)((c >> 4) & 511);
    int b = (int)(c >> 13);
    const float* src = X + (((size_t)b * 512 + t) * 128 + k0);
    size_t dst = ((size_t)(t * 256 + b)) * 128 + k0;
#pragma unroll
    for (int i = 0; i < 8; i++) {
        float x = src[i];
        __nv_bfloat16 h = __float2bfloat16(x);
        g_Xh[dst + i] = h;
        g_Xl[dst + i] = __float2bfloat16(x - __bfloat162float(h));
    }
}

__global__ void conv_w(const float* __restrict__ W) {
    unsigned c = blockIdx.x * blockDim.x + threadIdx.x;
    int k0 = (c & 15) * 8;
    int gt = (int)(c >> 4);
    const float* src = W + ((size_t)gt * 128 + k0);
    size_t dst = (size_t)gt * 128 + k0;
#pragma unroll
    for (int i = 0; i < 8; i++) {
        float x = src[i];
        __nv_bfloat16 h = __float2bfloat16(x);
        g_Wh[dst + i] = h;
        g_Wl[dst + i] = __float2bfloat16(x - __bfloat162float(h));
    }
}

// out_W split (128x128 -> g_Oh/g_Ol); 2048 chunks
__global__ void conv_ow(const float* __restrict__ W) {
    unsigned c = blockIdx.x * blockDim.x + threadIdx.x;
    size_t base = (size_t)c * 8;
#pragma unroll
    for (int i = 0; i < 8; i++) {
        float x = W[base + i];
        __nv_bfloat16 h = __float2bfloat16(x);
        g_Oh[base + i] = h;
        g_Ol[base + i] = __float2bfloat16(x - __bfloat162float(h));
    }
}

// Hdec split into the REUSED g_Xh/g_Xl (straight copy, same indexing)
__global__ void conv_h(int dummy) {
    unsigned c = blockIdx.x * blockDim.x + threadIdx.x;
    size_t base = (size_t)c * 8;
#pragma unroll
    for (int i = 0; i < 8; i++) {
        float x = g_Hdec[base + i];
        __nv_bfloat16 h = __float2bfloat16(x);
        g_Xh[base + i] = h;
        g_Xl[base + i] = __float2bfloat16(x - __bfloat162float(h));
    }
}

// ---------------------------------------------------------------------------
// HMMA gi GEMM (split-bf16, 3 terms): g_Genc[r][g] = x[r,:].W[g,:] + bias
// ---------------------------------------------------------------------------
#define APAD 136
#define MMA_SMEM (4 * 128 * APAD * 2)   // 139264 B

__global__ void __launch_bounds__(256) mma_gemm_gi(const float* __restrict__ bias) {
    extern __shared__ __align__(16) __nv_bfloat16 sm[];
    __nv_bfloat16* sAh = sm;
    __nv_bfloat16* sAl = sm + 128 * APAD;
    __nv_bfloat16* sBh = sm + 2 * 128 * APAD;
    __nv_bfloat16* sBl = sm + 3 * 128 * APAD;
    __shared__ float bias_s[128];
    int tid = threadIdx.x;
    int wid = tid >> 5, lane = tid & 31;
    int n0 = blockIdx.x * 128;
    size_t rBase = (size_t)blockIdx.y * 128;

    if (tid < 128) bias_s[tid] = bias[n0 + tid];

#pragma unroll
    for (int i = 0; i < 8; i++) {
        int c = tid + i * 256;
        int r = c >> 4, k0 = (c & 15) * 8;
        uint4 vh = *(const uint4*)&g_Xh[(rBase + r) * 128 + k0];
        uint4 vl = *(const uint4*)&g_Xl[(rBase + r) * 128 + k0];
        *(uint4*)&sAh[r * APAD + k0] = vh;
        *(uint4*)&sAl[r * APAD + k0] = vl;
    }
#pragma unroll
    for (int i = 0; i < 8; i++) {
        int c = tid + i * 256;
        int r = c >> 4, k0 = (c & 15) * 8;
        uint4 vh = *(const uint4*)&g_Wh[(size_t)(n0 + r) * 128 + k0];
        uint4 vl = *(const uint4*)&g_Wl[(size_t)(n0 + r) * 128 + k0];
        *(uint4*)&sBh[r * APAD + k0] = vh;
        *(uint4*)&sBl[r * APAD + k0] = vl;
    }
    __syncthreads();

    int wm = wid >> 1, wn = wid & 1;
    float d[2][8][4];
#pragma unroll
    for (int mf = 0; mf < 2; mf++)
#pragma unroll
        for (int nf = 0; nf < 8; nf++)
#pragma unroll
            for (int e = 0; e < 4; e++) d[mf][nf][e] = 0.0f;

    int aRow = wm * 32 + (lane & 7) + ((lane >> 3) & 1) * 8;
    int aCol = (lane >> 4) * 8;
    int bRow = wn * 64 + (lane & 7) + ((lane >= 16) ? 8 : 0);
    int bCol = ((lane >> 3) & 1) * 8;

    for (int ks = 0; ks < 8; ks++) {
        int k0 = ks * 16;
        unsigned ah[2][4], al[2][4];
#pragma unroll
        for (int mf = 0; mf < 2; mf++) {
            unsigned off = (unsigned)((aRow + mf * 16) * APAD + k0 + aCol) * 2u;
            ldsm4(ah[mf], smaddr(sAh) + off);
            ldsm4(al[mf], smaddr(sAl) + off);
        }
#pragma unroll
        for (int np = 0; np < 4; np++) {
            unsigned off = (unsigned)((bRow + np * 16) * APAD + k0 + bCol) * 2u;
            unsigned bh[4], bl[4];
            ldsm4(bh, smaddr(sBh) + off);
            ldsm4(bl, smaddr(sBl) + off);
#pragma unroll
            for (int mf = 0; mf < 2; mf++) {
                mma16816(d[mf][np * 2],     ah[mf], bh[0], bh[1]);
                mma16816(d[mf][np * 2 + 1], ah[mf], bh[2], bh[3]);
                mma16816(d[mf][np * 2],     ah[mf], bl[0], bl[1]);
                mma16816(d[mf][np * 2 + 1], ah[mf], bl[2], bl[3]);
                mma16816(d[mf][np * 2],     al[mf], bh[0], bh[1]);
                mma16816(d[mf][np * 2 + 1], al[mf], bh[2], bh[3]);
            }
        }
    }

    int group = lane >> 2, tg = lane & 3;
#pragma unroll
    for (int mf = 0; mf < 2; mf++) {
#pragma unroll
        for (int nf = 0; nf < 8; nf++) {
            int row = wm * 32 + mf * 16 + group;
            int col = wn * 64 + nf * 8 + tg * 2;
            size_t r = rBase + row;
            float b0 = bias_s[col], b1 = bias_s[col + 1];
            float2 v0 = make_float2(d[mf][nf][0] + b0, d[mf][nf][1] + b1);
            float2 v1 = make_float2(d[mf][nf][2] + b0, d[mf][nf][3] + b1);
            *(float2*)&g_Genc[r * 384 + n0 + col] = v0;
            *(float2*)&g_Genc[(r + 8) * 384 + n0 + col] = v1;
        }
    }
}

// ---------------------------------------------------------------------------
// HMMA out GEMM (split-bf16): o[r][f] = Hdec[r,:].out_W[f,:] + out_b[f]
// A = g_Xh/g_Xl (now holding Hdec split). B = g_Oh/g_Ol. N=128 (one tile).
// Epilogue: time-reversed output layout (identical to fp32 gemm_out).
// ---------------------------------------------------------------------------
__global__ void __launch_bounds__(256) mma_gemm_out(const float* __restrict__ bias,
                                                    float* __restrict__ out) {
    extern __shared__ __align__(16) __nv_bfloat16 sm[];
    __nv_bfloat16* sAh = sm;
    __nv_bfloat16* sAl = sm + 128 * APAD;
    __nv_bfloat16* sBh = sm + 2 * 128 * APAD;
    __nv_bfloat16* sBl = sm + 3 * 128 * APAD;
    __shared__ float bias_s[128];
    int tid = threadIdx.x;
    int wid = tid >> 5, lane = tid & 31;
    size_t rBase = (size_t)blockIdx.x * 128;

    if (tid < 128) bias_s[tid] = bias[tid];

#pragma unroll
    for (int i = 0; i < 8; i++) {
        int c = tid + i * 256;
        int r = c >> 4, k0 = (c & 15) * 8;
        uint4 vh = *(const uint4*)&g_Xh[(rBase + r) * 128 + k0];
        uint4 vl = *(const uint4*)&g_Xl[(rBase + r) * 128 + k0];
        *(uint4*)&sAh[r * APAD + k0] = vh;
        *(uint4*)&sAl[r * APAD + k0] = vl;
    }
#pragma unroll
    for (int i = 0; i < 8; i++) {
        int c = tid + i * 256;
        int r = c >> 4, k0 = (c & 15) * 8;
        uint4 vh = *(const uint4*)&g_Oh[(size_t)r * 128 + k0];
        uint4 vl = *(const uint4*)&g_Ol[(size_t)r * 128 + k0];
        *(uint4*)&sBh[r * APAD + k0] = vh;
        *(uint4*)&sBl[r * APAD + k0] = vl;
    }
    __syncthreads();

    int wm = wid >> 1, wn = wid & 1;
    float d[2][8][4];
#pragma unroll
    for (int mf = 0; mf < 2; mf++)
#pragma unroll
        for (int nf = 0; nf < 8; nf++)
#pragma unroll
            for (int e = 0; e < 4; e++) d[mf][nf][e] = 0.0f;

    int aRow = wm * 32 + (lane & 7) + ((lane >> 3) & 1) * 8;
    int aCol = (lane >> 4) * 8;
    int bRow = wn * 64 + (lane & 7) + ((lane >= 16) ? 8 : 0);
    int bCol = ((lane >> 3) & 1) * 8;

    for (int ks = 0; ks < 8; ks++) {
        int k0 = ks * 16;
        unsigned ah[2][4], al[2][4];
#pragma unroll
        for (int mf = 0; mf < 2; mf++) {
            unsigned off = (unsigned)((aRow + mf * 16) * APAD + k0 + aCol) * 2u;
            ldsm4(ah[mf], smaddr(sAh) + off);
            ldsm4(al[mf], smaddr(sAl) + off);
        }
#pragma unroll
        for (int np = 0; np < 4; np++) {
            unsigned off = (unsigned)((bRow + np * 16) * APAD + k0 + bCol) * 2u;
            unsigned bh[4], bl[4];
            ldsm4(bh, smaddr(sBh) + off);
            ldsm4(bl, smaddr(sBl) + off);
#pragma unroll
            for (int mf = 0; mf < 2; mf++) {
                mma16816(d[mf][np * 2],     ah[mf], bh[0], bh[1]);
                mma16816(d[mf][np * 2 + 1], ah[mf], bh[2], bh[3]);
                mma16816(d[mf][np * 2],     ah[mf], bl[0], bl[1]);
                mma16816(d[mf][np * 2 + 1], ah[mf], bl[2], bl[3]);
                mma16816(d[mf][np * 2],     al[mf], bh[0], bh[1]);
                mma16816(d[mf][np * 2 + 1], al[mf], bh[2], bh[3]);
            }
        }
    }

    // Epilogue with time reversal: r = i*256+b -> output[b][511-i][:]
    int group = lane >> 2, tg = lane & 3;
#pragma unroll
    for (int mf = 0; mf < 2; mf++) {
#pragma unroll
        for (int nf = 0; nf < 8; nf++) {
            int row = wm * 32 + mf * 16 + group;
            int col = wn * 64 + nf * 8 + tg * 2;
            float b0 = bias_s[col], b1 = bias_s[col + 1];
            size_t r0 = rBase + row;
            size_t r1 = r0 + 8;
            int is0 = (int)(r0 >> 8), bb0 = (int)(r0 & 255);
            int is1 = (int)(r1 >> 8), bb1 = (int)(r1 & 255);
            size_t o0 = (size_t)(bb0 * 512 + (511 - is0)) * 128;
            size_t o1 = (size_t)(bb1 * 512 + (511 - is1)) * 128;
            float2 v0 = make_float2(d[mf][nf][0] + b0, d[mf][nf][1] + b1);
            float2 v1 = make_float2(d[mf][nf][2] + b0, d[mf][nf][3] + b1);
            *(float2*)&out[OFF_OUT + o0 + col] = v0;
            *(float2*)&out[OFF_OUT + o1 + col] = v1;
        }
    }
}

// ---------------------------------------------------------------------------
// Fold: Mf = dec_Wih @ out_W ; bf = dec_bih + dec_Wih @ out_b
// ---------------------------------------------------------------------------
__global__ void fold_kernel(const float* __restrict__ dWih, const float* __restrict__ outW,
                            const float* __restrict__ outb, const float* __restrict__ dbih) {
    int g = blockIdx.x, j = threadIdx.x;
    __shared__ float wrow[128];
    __shared__ float red[128];
    wrow[j] = dWih[g * 128 + j];
    __syncthreads();
    float acc = 0.0f;
#pragma unroll 8
    for (int f = 0; f < 128; f++) acc = fmaf(wrow[f], outW[f * 128 + j], acc);
    g_Mf[g * 128 + j] = acc;
    red[j] = wrow[j] * outb[j];
    __syncthreads();
    for (int s = 64; s > 0; s >>= 1) {
        if (j < s) red[j] += red[j + s];
        __syncthreads();
    }
    if (j == 0) g_bf[g] = dbih[g] + red[0];
}

// ---------------------------------------------------------------------------
// Encoder recurrence (R5-exact scalar)
// ---------------------------------------------------------------------------
__global__ void __launch_bounds__(384, 1) enc_kernel(const float* __restrict__ Whh,
                                                     const float* __restrict__ bhh) {
    __shared__ float h_sm[2][128];
    __shared__ float gh_sm[2][384];
    int g = threadIdx.x;
    int b0 = blockIdx.x * 2;
    float w[128];
#pragma unroll
    for (int k = 0; k < 128; k += 4) {
        float4 v = *(const float4*)&Whh[(size_t)g * 128 + k];
        w[k] = v.x; w[k + 1] = v.y; w[k + 2] = v.z; w[k + 3] = v.w;
    }
    float bg = bhh[g];
    int bb = g >> 7, j = g & 127;
    if (g < 256) h_sm[bb][j] = 0.0f;
    __syncthreads();

    for (int t = 0; t < 512; t++) {
        float gi_r = 0.f, gi_z = 0.f, gi_n = 0.f;
        if (g < 256) {
            const float* gp = g_Genc + ((size_t)t * 256 + b0 + bb) * 384;
            gi_r = gp[j]; gi_z = gp[128 + j]; gi_n = gp[256 + j];
        }
        float a0 = bg, a1 = bg;
#pragma unroll
        for (int k = 0; k < 128; k += 4) {
            float4 h0 = *(const float4*)&h_sm[0][k];
            float4 h1 = *(const float4*)&h_sm[1][k];
            a0 = fmaf(w[k], h0.x, a0);     a1 = fmaf(w[k], h1.x, a1);
            a0 = fmaf(w[k + 1], h0.y, a0); a1 = fmaf(w[k + 1], h1.y, a1);
            a0 = fmaf(w[k + 2], h0.z, a0); a1 = fmaf(w[k + 2], h1.z, a1);
            a0 = fmaf(w[k + 3], h0.w, a0); a1 = fmaf(w[k + 3], h1.w, a1);
        }
        gh_sm[0][g] = a0;
        gh_sm[1][g] = a1;
        __syncthreads();
        if (g < 256) {
            float r = sigf(gi_r + gh_sm[bb][j]);
            float z = sigf(gi_z + gh_sm[bb][128 + j]);
            float n = tanhf(gi_n + r * gh_sm[bb][256 + j]);
            h_sm[bb][j] = (1.0f - z) * n + z * h_sm[bb][j];
        }
        __syncthreads();
    }
    if (g < 256) g_Henc[(b0 + bb) * 128 + j] = h_sm[bb][j];
}

// ---------------------------------------------------------------------------
// Decoder recurrence (R7-exact, best measured)
// ---------------------------------------------------------------------------
__global__ void __launch_bounds__(384, 1) dec_kernel(const float* __restrict__ Whh,
                                                     const float* __restrict__ bhh) {
    extern __shared__ __align__(16) unsigned char dsm[];
    ulonglong2* wq = (ulonglong2*)dsm;                 // [32][384] -> 196608 B
    float* hsm = (float*)(dsm + 196608);
    float* gis = hsm + 256;
    float* ghs = gis + 768;
    int g = threadIdx.x;
    int b0 = blockIdx.x * 2;
    int bb = g >> 7, j = g & 127;

    ull w2[64];
    {
        const ull* wrow = (const ull*)g_Mf + (size_t)g * 64;
#pragma unroll
        for (int kp = 0; kp < 64; kp++) w2[kp] = wrow[kp];
    }
    float bfg = g_bf[g];
    float bhg = bhh[g];

    for (int idx = g; idx < 384 * 32; idx += 384) {
        int gg = idx >> 5, q = idx & 31;
        wq[q * 384 + gg] = ((const ulonglong2*)Whh)[(size_t)gg * 32 + q];
    }
    if (g < 256) {
        float h_init = g_Henc[b0 * 128 + g];
        hsm[g] = h_init;
        g_Hdec[((size_t)0 * 256 + b0 + bb) * 128 + j] = h_init;
    }
    __syncthreads();

    for (int i = 0; i < 512; i++) {
        ull gi0 = pk2(bfg, 0.f), gi1 = pk2(bfg, 0.f);
        ull gh0 = pk2(bhg, 0.f), gh1 = pk2(bhg, 0.f);
#pragma unroll
        for (int grp = 0; grp < 16; grp++) {
            ulonglong2 wvA = wq[(2 * grp) * 384 + g];
            ulonglong2 wvB = wq[(2 * grp + 1) * 384 + g];
            ulonglong2 h0A = *(const ulonglong2*)&hsm[8 * grp];
            ulonglong2 h0B = *(const ulonglong2*)&hsm[8 * grp + 4];
            ulonglong2 h1A = *(const ulonglong2*)&hsm[128 + 8 * grp];
            ulonglong2 h1B = *(const ulonglong2*)&hsm[128 + 8 * grp + 4];
            gi0 = f2fma(w2[4 * grp],     h0A.x, gi0);
            gi1 = f2fma(w2[4 * grp],     h1A.x, gi1);
            gi0 = f2fma(w2[4 * grp + 1], h0A.y, gi0);
            gi1 = f2fma(w2[4 * grp + 1], h1A.y, gi1);
            gi0 = f2fma(w2[4 * grp + 2], h0B.x, gi0);
            gi1 = f2fma(w2[4 * grp + 2], h1B.x, gi1);
            gi0 = f2fma(w2[4 * grp + 3], h0B.y, gi0);
            gi1 = f2fma(w2[4 * grp + 3], h1B.y, gi1);
            gh0 = f2fma(wvA.x, h0A.x, gh0);
            gh1 = f2fma(wvA.x, h1A.x, gh1);
            gh0 = f2fma(wvA.y, h0A.y, gh0);
            gh1 = f2fma(wvA.y, h1A.y, gh1);
            gh0 = f2fma(wvB.x, h0B.x, gh0);
            gh1 = f2fma(wvB.x, h1B.x, gh1);
            gh0 = f2fma(wvB.y, h0B.y, gh0);
            gh1 = f2fma(wvB.y, h1B.y, gh1);
        }
        gis[g] = psum(gi0); gis[384 + g] = psum(gi1);
        ghs[g] = psum(gh0); ghs[384 + g] = psum(gh1);
        __syncthreads();
        if (g < 256) {
            int base = bb * 384;
            float r = sigf(gis[base + j] + ghs[base + j]);
            float z = sigf(gis[base + 128 + j] + ghs[base + 128 + j]);
            float n = tanhf(gis[base + 256 + j] + r * ghs[base + 256 + j]);
            float h_new = (1.0f - z) * n + z * hsm[g];
            hsm[g] = h_new;
            if (i < 511)
                g_Hdec[((size_t)(i + 1) * 256 + b0 + bb) * 128 + j] = h_new;
        }
        __syncthreads();
    }
}

// ---------------------------------------------------------------------------
// Epilogues (unchanged)
// ---------------------------------------------------------------------------
__device__ __forceinline__ float bsum(float v, float* red) {
    int t = threadIdx.x;
    __syncthreads();
    red[t] = v;
    __syncthreads();
    for (int s = 128; s > 0; s >>= 1) {
        if (t < s) red[t] += red[t + s];
        __syncthreads();
    }
    return red[0];
}

__global__ void __launch_bounds__(256) epiA(
    const float* __restrict__ X,
    const float* __restrict__ protos,
    const float* __restrict__ lnzw, const float* __restrict__ lnzb,
    const float* __restrict__ lnpw, const float* __restrict__ lnpb,
    const float* __restrict__ lnaw, const float* __restrict__ lnab,
    const float* __restrict__ beta,
    const float* __restrict__ e1W, const float* __restrict__ e1b,
    const float* __restrict__ e2W, const float* __restrict__ e2b,
    float* __restrict__ out) {
    int b = blockIdx.x, t = threadIdx.x;
    __shared__ float red[256];
    __shared__ float zln[128];
    __shared__ float pl[8][128];
    __shared__ float dotk[8];
    __shared__ float attnv[8];
    __shared__ float zfull[129];
    __shared__ float h1s[10];
    __shared__ float lg[4];

    const float* a = X + (size_t)b * 65536;
    const float* o = out + OFF_OUT + (size_t)b * 65536;
    float sab = 0.f, saa = 0.f, sbb = 0.f;
    for (int i = t; i < 65536; i += 256) {
        float av = a[i], bv = o[i];
        sab = fmaf(av, bv, sab);
        saa = fmaf(av, av, saa);
        sbb = fmaf(bv, bv, sbb);
    }
    sab = bsum(sab, red);
    saa = bsum(saa, red);
    sbb = bsum(sbb, red);
    float rc = sab / (fmaxf(sqrtf(saa), 1e-8f) * fmaxf(sqrtf(sbb), 1e-8f));

    float h = (t < 128) ? g_Henc[b * 128 + t] : 0.0f;
    if (t < 128) out[OFF_HENC + b * 128 + t] = h;
    float mu = bsum(h, red) * (1.0f / 128.0f);
    float d = (t < 128) ? (h - mu) : 0.0f;
    float var = bsum(d * d, red) * (1.0f / 128.0f);
    if (t < 128) zln[t] = lnzw[t] * d * rsqrtf(var + 1e-12f) + lnzb[t];

    for (int k = 0; k < 8; k++) {
        float p = (t < 128) ? protos[k * 128 + t] : 0.0f;
        float pu = bsum(p, red) * (1.0f / 128.0f);
        float pd = (t < 128) ? (p - pu) : 0.0f;
        float pv = bsum(pd * pd, red) * (1.0f / 128.0f);
        if (t < 128) pl[k][t] = lnpw[t] * pd * rsqrtf(pv + 1e-12f) + lnpb[t];
    }
    __syncthreads();

    for (int k = 0; k < 8; k++) {
        float pp = (t < 128) ? zln[t] * pl[k][t] : 0.0f;
        float s = bsum(pp, red);
        if (t == 0) dotk[k] = s * 0.08838834764831845f;
    }
    __syncthreads();
    if (t < 8) {
        float m = -1e30f;
        for (int kk = 0; kk < 8; kk++) m = fmaxf(m, dotk[kk]);
        float s = 0.f;
        for (int kk = 0; kk < 8; kk++) s += expf(dotk[kk] - m);
        attnv[t] = expf(dotk[t] - m) / s;
    }
    __syncthreads();

    float zacc = 0.0f;
    for (int k = 0; k < 8; k++) {
        float v = (t < 128) ? (beta[k * 128 + t] + attnv[k] * h) : 0.0f;
        float vu = bsum(v, red) * (1.0f / 128.0f);
        float vd = (t < 128) ? (v - vu) : 0.0f;
        float vv = bsum(vd * vd, red) * (1.0f / 128.0f);
        if (t < 128) {
            float dval = lnaw[t] * vd * rsqrtf(vv + 1e-12f) + lnab[t];
            out[OFF_DIS + ((size_t)b * 8 + k) * 128 + t] = dval;
            zacc += dval;
        }
    }
    if (t < 128) {
        float zv = zacc * 0.125f;
        zfull[t] = zv;
        out[OFF_Z + (size_t)b * 129 + t] = zv;
    }
    if (t == 0) {
        zfull[128] = rc;
        out[OFF_Z + (size_t)b * 129 + 128] = rc;
    }
    __syncthreads();

    if (t < 10) {
        float acc = e1b[t];
        for (int i = 0; i < 129; i++) acc = fmaf(e1W[t * 129 + i], zfull[i], acc);
        h1s[t] = tanhf(acc);
    }
    __syncthreads();
    if (t < 4) {
        float acc = e2b[t];
        for (int i = 0; i < 10; i++) acc = fmaf(e2W[t * 10 + i], h1s[i], acc);
        lg[t] = acc;
    }
    __syncthreads();
    if (t < 4) {
        float m = fmaxf(fmaxf(lg[0], lg[1]), fmaxf(lg[2], lg[3]));
        float s = expf(lg[0] - m) + expf(lg[1] - m) + expf(lg[2] - m) + expf(lg[3] - m);
        out[OFF_GAMMA + (size_t)b * 4 + t] = expf(lg[t] - m) / s;
    }
}

__global__ void epiB(float* __restrict__ out, const int* __restrict__ perm) {
    int b = blockIdx.x;
    for (int e = threadIdx.x; e < 1024; e += blockDim.x) {
        int k = e >> 7, j = e & 127;
        int src = perm[k * 256 + b];
        out[OFF_DISP + ((size_t)b * 8 + k) * 128 + j] =
            out[OFF_DIS + ((size_t)src * 8 + k) * 128 + j];
    }
}

// ---------------------------------------------------------------------------
extern "C" void kernel_launch(void* const* d_in, const int* in_sizes, int n_in,
                              void* d_out, int out_size) {
    const float* input   = (const float*)d_in[0];
    const float* enc_Wih = (const float*)d_in[1];
    const float* enc_Whh = (const float*)d_in[2];
    const float* enc_bih = (const float*)d_in[3];
    const float* enc_bhh = (const float*)d_in[4];
    const float* dec_Wih = (const float*)d_in[5];
    const float* dec_Whh = (const float*)d_in[6];
    const float* dec_bih = (const float*)d_in[7];
    const float* dec_bhh = (const float*)d_in[8];
    const float* out_W   = (const float*)d_in[9];
    const float* out_b   = (const float*)d_in[10];
    const float* protos  = (const float*)d_in[11];
    const float* lnz_w   = (const float*)d_in[12];
    const float* lnz_b   = (const float*)d_in[13];
    const float* lnp_w   = (const float*)d_in[14];
    const float* lnp_b   = (const float*)d_in[15];
    const float* lna_w   = (const float*)d_in[16];
    const float* lna_b   = (const float*)d_in[17];
    const float* beta    = (const float*)d_in[18];
    const float* est1_W  = (const float*)d_in[19];
    const float* est1_b  = (const float*)d_in[20];
    const float* est2_W  = (const float*)d_in[21];
    const float* est2_b  = (const float*)d_in[22];
    float* out = (float*)d_out;

    int* perm_ptr = nullptr;
    cudaGetSymbolAddress((void**)&perm_ptr, g_perm);

    cudaFuncSetAttribute(dec_kernel, cudaFuncAttributeMaxDynamicSharedMemorySize, 204288);
    cudaFuncSetAttribute(mma_gemm_gi, cudaFuncAttributeMaxDynamicSharedMemorySize, MMA_SMEM);
    cudaFuncSetAttribute(mma_gemm_out, cudaFuncAttributeMaxDynamicSharedMemorySize, MMA_SMEM);

    // 1. bf16 split conversion of X, enc_Wih, out_W
    conv_x<<<8192, 256>>>(input);
    conv_w<<<24, 256>>>(enc_Wih);
    conv_ow<<<8, 256>>>(out_W);
    // 2. Tensor-core gi GEMM (split-bf16, 3 terms)
    mma_gemm_gi<<<dim3(3, 1024), 256, MMA_SMEM>>>(enc_bih);
    // 3. Encoder recurrence
    enc_kernel<<<128, 384>>>(enc_Whh, enc_bhh);
    // 4. Fold output projection into decoder input weights
    fold_kernel<<<384, 128>>>(dec_Wih, out_W, out_b, dec_bih);
    // 5. Decoder recurrence
    dec_kernel<<<128, 384, 204288>>>(dec_Whh, dec_bhh);
    // 6. Split Hdec into reused g_Xh/g_Xl, then tensor-core out GEMM
    conv_h<<<8192, 256>>>(0);
    mma_gemm_out<<<1024, 256, MMA_SMEM>>>(out_b, out);
    // 7. JAX-exact permutations
    perm_kernel<<<1, 256>>>(perm_ptr);
    // 8. Epilogue
    epiA<<<256, 256>>>(input, protos, lnz_w, lnz_b, lnp_w, lnp_b, lna_w, lna_b,
                       beta, est1_W, est1_b, est2_W, est2_b, out);
    // 9. dis_perm gather
    epiB<<<256, 256>>>(out, perm_ptr);
}

// round 14
// speedup vs baseline: 1.0636x; 1.0636x over previous
#include <cuda_runtime.h>
#include <cuda_bf16.h>
#include <math.h>
#include <stdint.h>
#include <stddef.h>

// Problem dims
#define Bsz 256
#define Ssz 512
#define Fdim 128
#define Hdim 128
#define G3  384   // 3*H

// Output layout (tuple flattened): h_enc, output, z, gamma, dis, dis_perm
#define OFF_HENC  ((size_t)0)
#define OFF_OUT   ((size_t)32768)                       // 256*128
#define OFF_Z     ((size_t)(32768 + 16777216))          // + 256*512*128
#define OFF_GAMMA ((size_t)(OFF_Z + 256*129))
#define OFF_DIS   ((size_t)(OFF_GAMMA + 256*4))
#define OFF_DISP  ((size_t)(OFF_DIS + 256*8*128))

typedef unsigned long long ull;

// Scratch (device globals; no allocations allowed)
__device__ float g_Genc[(size_t)Ssz * Bsz * G3];    // [t][b][g]  192 MB
__device__ float g_Henc[Bsz * Hdim];
__device__ float g_Mf[G3 * Hdim];
__device__ float g_bf[G3];
__device__ int   g_perm[8 * Bsz];
// bf16 split operands. g_Xh/g_Xl are REUSED: X split for gi GEMM, then the
// decoder writes its h-trajectory split directly into them for the out GEMM.
__device__ __nv_bfloat16 g_Xh[(size_t)131072 * 128];   // 33.5 MB
__device__ __nv_bfloat16 g_Xl[(size_t)131072 * 128];
__device__ __nv_bfloat16 g_Wh[G3 * 128];
__device__ __nv_bfloat16 g_Wl[G3 * 128];
__device__ __nv_bfloat16 g_Oh[128 * 128];              // out_W split
__device__ __nv_bfloat16 g_Ol[128 * 128];

// Fast gate math: __expf is a single MUFU.EX2-based approx (~2 ulp).
__device__ __forceinline__ float sigf(float x) { return 1.0f / (1.0f + __expf(-x)); }
__device__ __forceinline__ float tanh_fast(float x) {
    float t = __expf(-2.0f * fabsf(x));      // in (0,1], no overflow
    float r = (1.0f - t) / (1.0f + t);
    return copysignf(r, x);
}

// ---- packed f32x2 helpers (used by dec only) ----
__device__ __forceinline__ ull pk2(float lo, float hi) {
    ull r; asm("mov.b64 %0, {%1, %2};" : "=l"(r) : "f"(lo), "f"(hi)); return r;
}
__device__ __forceinline__ ull f2fma(ull a, ull b, ull c) {
    ull d; asm("fma.rn.f32x2 %0, %1, %2, %3;" : "=l"(d) : "l"(a), "l"(b), "l"(c)); return d;
}
__device__ __forceinline__ float psum(ull v) {
    float a, b; asm("mov.b64 {%0, %1}, %2;" : "=f"(a), "=f"(b) : "l"(v)); return a + b;
}

__device__ __forceinline__ unsigned smaddr(const void* p) {
    unsigned a;
    asm("{ .reg .u64 t; cvta.to.shared.u64 t, %1; cvt.u32.u64 %0, t; }" : "=r"(a) : "l"(p));
    return a;
}

__device__ __forceinline__ void ldsm4(unsigned* f, unsigned addr) {
    asm volatile("ldmatrix.sync.aligned.m8n8.x4.shared.b16 {%0,%1,%2,%3}, [%4];"
                 : "=r"(f[0]), "=r"(f[1]), "=r"(f[2]), "=r"(f[3]) : "r"(addr));
}
__device__ __forceinline__ void mma16816(float* d, const unsigned* a, unsigned b0, unsigned b1) {
    asm volatile(
        "mma.sync.aligned.m16n8k16.row.col.f32.bf16.bf16.f32 "
        "{%0,%1,%2,%3}, {%4,%5,%6,%7}, {%8,%9}, {%0,%1,%2,%3};"
        : "+f"(d[0]), "+f"(d[1]), "+f"(d[2]), "+f"(d[3])
        : "r"(a[0]), "r"(a[1]), "r"(a[2]), "r"(a[3]), "r"(b0), "r"(b1));
}

// ---------------------------------------------------------------------------
// Threefry2x32 (exact JAX constants)
// ---------------------------------------------------------------------------
__device__ __forceinline__ uint2 threefry(unsigned k0, unsigned k1,
                                          unsigned x0, unsigned x1) {
    unsigned ks2 = k0 ^ k1 ^ 0x1BD11BDAu;
    x0 += k0; x1 += k1;
#define TFR(r) { x0 += x1; x1 = (x1 << (r)) | (x1 >> (32 - (r))); x1 ^= x0; }
    TFR(13) TFR(15) TFR(26) TFR(6)   x0 += k1;  x1 += ks2 + 1u;
    TFR(17) TFR(29) TFR(16) TFR(24)  x0 += ks2; x1 += k0 + 2u;
    TFR(13) TFR(15) TFR(26) TFR(6)   x0 += k0;  x1 += k1 + 3u;
    TFR(17) TFR(29) TFR(16) TFR(24)  x0 += k1;  x1 += ks2 + 4u;
    TFR(13) TFR(15) TFR(26) TFR(6)   x0 += ks2; x1 += k0 + 5u;
#undef TFR
    return make_uint2(x0, x1);
}

__global__ void perm_kernel(int* __restrict__ perm) {
    __shared__ unsigned sk[8][2];
    __shared__ unsigned bits[256];
    int t = threadIdx.x;
    if (t < 8) {
        uint2 pk = threefry(0u, 42u, 0u, (unsigned)t);
        uint2 s  = threefry(pk.x, pk.y, 0u, 1u);
        sk[t][0] = s.x; sk[t][1] = s.y;
    }
    __syncthreads();
    for (int k = 0; k < 8; k++) {
        uint2 y = threefry(sk[k][0], sk[k][1], 0u, (unsigned)t);
        bits[t] = y.x ^ y.y;
        __syncthreads();
        unsigned mine = bits[t];
        int rank = 0;
        for (int j = 0; j < 256; j++) {
            unsigned o = bits[j];
            rank += (o < mine) || (o == mine && j < t);
        }
        perm[k * 256 + rank] = t;
        __syncthreads();
    }
}

// ---------------------------------------------------------------------------
// bf16 split conversions
// ---------------------------------------------------------------------------
__global__ void conv_x(const float* __restrict__ X) {
    unsigned c = blockIdx.x * blockDim.x + threadIdx.x;
    int k0 = (c & 15) * 8;
    int t = (int)((c >> 4) & 511);
    int b = (int)(c >> 13);
    const float* src = X + (((size_t)b * 512 + t) * 128 + k0);
    size_t dst = ((size_t)(t * 256 + b)) * 128 + k0;
#pragma unroll
    for (int i = 0; i < 8; i++) {
        float x = src[i];
        __nv_bfloat16 h = __float2bfloat16(x);
        g_Xh[dst + i] = h;
        g_Xl[dst + i] = __float2bfloat16(x - __bfloat162float(h));
    }
}

__global__ void conv_w(const float* __restrict__ W) {
    unsigned c = blockIdx.x * blockDim.x + threadIdx.x;
    int k0 = (c & 15) * 8;
    int gt = (int)(c >> 4);
    const float* src = W + ((size_t)gt * 128 + k0);
    size_t dst = (size_t)gt * 128 + k0;
#pragma unroll
    for (int i = 0; i < 8; i++) {
        float x = src[i];
        __nv_bfloat16 h = __float2bfloat16(x);
        g_Wh[dst + i] = h;
        g_Wl[dst + i] = __float2bfloat16(x - __bfloat162float(h));
    }
}

__global__ void conv_ow(const float* __restrict__ W) {
    unsigned c = blockIdx.x * blockDim.x + threadIdx.x;
    size_t base = (size_t)c * 8;
#pragma unroll
    for (int i = 0; i < 8; i++) {
        float x = W[base + i];
        __nv_bfloat16 h = __float2bfloat16(x);
        g_Oh[base + i] = h;
        g_Ol[base + i] = __float2bfloat16(x - __bfloat162float(h));
    }
}

// ---------------------------------------------------------------------------
// HMMA gi GEMM (split-bf16, 3 terms): g_Genc[r][g] = x[r,:].W[g,:] + bias
// ---------------------------------------------------------------------------
#define APAD 136
#define MMA_SMEM (4 * 128 * APAD * 2)   // 139264 B

__global__ void __launch_bounds__(256) mma_gemm_gi(const float* __restrict__ bias) {
    extern __shared__ __align__(16) __nv_bfloat16 sm[];
    __nv_bfloat16* sAh = sm;
    __nv_bfloat16* sAl = sm + 128 * APAD;
    __nv_bfloat16* sBh = sm + 2 * 128 * APAD;
    __nv_bfloat16* sBl = sm + 3 * 128 * APAD;
    __shared__ float bias_s[128];
    int tid = threadIdx.x;
    int wid = tid >> 5, lane = tid & 31;
    int n0 = blockIdx.x * 128;
    size_t rBase = (size_t)blockIdx.y * 128;

    if (tid < 128) bias_s[tid] = bias[n0 + tid];

#pragma unroll
    for (int i = 0; i < 8; i++) {
        int c = tid + i * 256;
        int r = c >> 4, k0 = (c & 15) * 8;
        uint4 vh = *(const uint4*)&g_Xh[(rBase + r) * 128 + k0];
        uint4 vl = *(const uint4*)&g_Xl[(rBase + r) * 128 + k0];
        *(uint4*)&sAh[r * APAD + k0] = vh;
        *(uint4*)&sAl[r * APAD + k0] = vl;
    }
#pragma unroll
    for (int i = 0; i < 8; i++) {
        int c = tid + i * 256;
        int r = c >> 4, k0 = (c & 15) * 8;
        uint4 vh = *(const uint4*)&g_Wh[(size_t)(n0 + r) * 128 + k0];
        uint4 vl = *(const uint4*)&g_Wl[(size_t)(n0 + r) * 128 + k0];
        *(uint4*)&sBh[r * APAD + k0] = vh;
        *(uint4*)&sBl[r * APAD + k0] = vl;
    }
    __syncthreads();

    int wm = wid >> 1, wn = wid & 1;
    float d[2][8][4];
#pragma unroll
    for (int mf = 0; mf < 2; mf++)
#pragma unroll
        for (int nf = 0; nf < 8; nf++)
#pragma unroll
            for (int e = 0; e < 4; e++) d[mf][nf][e] = 0.0f;

    int aRow = wm * 32 + (lane & 7) + ((lane >> 3) & 1) * 8;
    int aCol = (lane >> 4) * 8;
    int bRow = wn * 64 + (lane & 7) + ((lane >= 16) ? 8 : 0);
    int bCol = ((lane >> 3) & 1) * 8;

    for (int ks = 0; ks < 8; ks++) {
        int k0 = ks * 16;
        unsigned ah[2][4], al[2][4];
#pragma unroll
        for (int mf = 0; mf < 2; mf++) {
            unsigned off = (unsigned)((aRow + mf * 16) * APAD + k0 + aCol) * 2u;
            ldsm4(ah[mf], smaddr(sAh) + off);
            ldsm4(al[mf], smaddr(sAl) + off);
        }
#pragma unroll
        for (int np = 0; np < 4; np++) {
            unsigned off = (unsigned)((bRow + np * 16) * APAD + k0 + bCol) * 2u;
            unsigned bh[4], bl[4];
            ldsm4(bh, smaddr(sBh) + off);
            ldsm4(bl, smaddr(sBl) + off);
#pragma unroll
            for (int mf = 0; mf < 2; mf++) {
                mma16816(d[mf][np * 2],     ah[mf], bh[0], bh[1]);
                mma16816(d[mf][np * 2 + 1], ah[mf], bh[2], bh[3]);
                mma16816(d[mf][np * 2],     ah[mf], bl[0], bl[1]);
                mma16816(d[mf][np * 2 + 1], ah[mf], bl[2], bl[3]);
                mma16816(d[mf][np * 2],     al[mf], bh[0], bh[1]);
                mma16816(d[mf][np * 2 + 1], al[mf], bh[2], bh[3]);
            }
        }
    }

    int group = lane >> 2, tg = lane & 3;
#pragma unroll
    for (int mf = 0; mf < 2; mf++) {
#pragma unroll
        for (int nf = 0; nf < 8; nf++) {
            int row = wm * 32 + mf * 16 + group;
            int col = wn * 64 + nf * 8 + tg * 2;
            size_t r = rBase + row;
            float b0 = bias_s[col], b1 = bias_s[col + 1];
            float2 v0 = make_float2(d[mf][nf][0] + b0, d[mf][nf][1] + b1);
            float2 v1 = make_float2(d[mf][nf][2] + b0, d[mf][nf][3] + b1);
            *(float2*)&g_Genc[r * 384 + n0 + col] = v0;
            *(float2*)&g_Genc[(r + 8) * 384 + n0 + col] = v1;
        }
    }
}

// ---------------------------------------------------------------------------
// HMMA out GEMM (split-bf16): o[r][f] = h[r,:].out_W[f,:] + out_b[f]
// A = g_Xh/g_Xl (holding the decoder h-trajectory split). B = g_Oh/g_Ol.
// ---------------------------------------------------------------------------
__global__ void __launch_bounds__(256) mma_gemm_out(const float* __restrict__ bias,
                                                    float* __restrict__ out) {
    extern __shared__ __align__(16) __nv_bfloat16 sm[];
    __nv_bfloat16* sAh = sm;
    __nv_bfloat16* sAl = sm + 128 * APAD;
    __nv_bfloat16* sBh = sm + 2 * 128 * APAD;
    __nv_bfloat16* sBl = sm + 3 * 128 * APAD;
    __shared__ float bias_s[128];
    int tid = threadIdx.x;
    int wid = tid >> 5, lane = tid & 31;
    size_t rBase = (size_t)blockIdx.x * 128;

    if (tid < 128) bias_s[tid] = bias[tid];

#pragma unroll
    for (int i = 0; i < 8; i++) {
        int c = tid + i * 256;
        int r = c >> 4, k0 = (c & 15) * 8;
        uint4 vh = *(const uint4*)&g_Xh[(rBase + r) * 128 + k0];
        uint4 vl = *(const uint4*)&g_Xl[(rBase + r) * 128 + k0];
        *(uint4*)&sAh[r * APAD + k0] = vh;
        *(uint4*)&sAl[r * APAD + k0] = vl;
    }
#pragma unroll
    for (int i = 0; i < 8; i++) {
        int c = tid + i * 256;
        int r = c >> 4, k0 = (c & 15) * 8;
        uint4 vh = *(const uint4*)&g_Oh[(size_t)r * 128 + k0];
        uint4 vl = *(const uint4*)&g_Ol[(size_t)r * 128 + k0];
        *(uint4*)&sBh[r * APAD + k0] = vh;
        *(uint4*)&sBl[r * APAD + k0] = vl;
    }
    __syncthreads();

    int wm = wid >> 1, wn = wid & 1;
    float d[2][8][4];
#pragma unroll
    for (int mf = 0; mf < 2; mf++)
#pragma unroll
        for (int nf = 0; nf < 8; nf++)
#pragma unroll
            for (int e = 0; e < 4; e++) d[mf][nf][e] = 0.0f;

    int aRow = wm * 32 + (lane & 7) + ((lane >> 3) & 1) * 8;
    int aCol = (lane >> 4) * 8;
    int bRow = wn * 64 + (lane & 7) + ((lane >= 16) ? 8 : 0);
    int bCol = ((lane >> 3) & 1) * 8;

    for (int ks = 0; ks < 8; ks++) {
        int k0 = ks * 16;
        unsigned ah[2][4], al[2][4];
#pragma unroll
        for (int mf = 0; mf < 2; mf++) {
            unsigned off = (unsigned)((aRow + mf * 16) * APAD + k0 + aCol) * 2u;
            ldsm4(ah[mf], smaddr(sAh) + off);
            ldsm4(al[mf], smaddr(sAl) + off);
        }
#pragma unroll
        for (int np = 0; np < 4; np++) {
            unsigned off = (unsigned)((bRow + np * 16) * APAD + k0 + bCol) * 2u;
            unsigned bh[4], bl[4];
            ldsm4(bh, smaddr(sBh) + off);
            ldsm4(bl, smaddr(sBl) + off);
#pragma unroll
            for (int mf = 0; mf < 2; mf++) {
                mma16816(d[mf][np * 2],     ah[mf], bh[0], bh[1]);
                mma16816(d[mf][np * 2 + 1], ah[mf], bh[2], bh[3]);
                mma16816(d[mf][np * 2],     ah[mf], bl[0], bl[1]);
                mma16816(d[mf][np * 2 + 1], ah[mf], bl[2], bl[3]);
                mma16816(d[mf][np * 2],     al[mf], bh[0], bh[1]);
                mma16816(d[mf][np * 2 + 1], al[mf], bh[2], bh[3]);
            }
        }
    }

    // Epilogue with time reversal: r = i*256+b -> output[b][511-i][:]
    int group = lane >> 2, tg = lane & 3;
#pragma unroll
    for (int mf = 0; mf < 2; mf++) {
#pragma unroll
        for (int nf = 0; nf < 8; nf++) {
            int row = wm * 32 + mf * 16 + group;
            int col = wn * 64 + nf * 8 + tg * 2;
            float b0 = bias_s[col], b1 = bias_s[col + 1];
            size_t r0 = rBase + row;
            size_t r1 = r0 + 8;
            int is0 = (int)(r0 >> 8), bb0 = (int)(r0 & 255);
            int is1 = (int)(r1 >> 8), bb1 = (int)(r1 & 255);
            size_t o0 = (size_t)(bb0 * 512 + (511 - is0)) * 128;
            size_t o1 = (size_t)(bb1 * 512 + (511 - is1)) * 128;
            float2 v0 = make_float2(d[mf][nf][0] + b0, d[mf][nf][1] + b1);
            float2 v1 = make_float2(d[mf][nf][2] + b0, d[mf][nf][3] + b1);
            *(float2*)&out[OFF_OUT + o0 + col] = v0;
            *(float2*)&out[OFF_OUT + o1 + col] = v1;
        }
    }
}

// ---------------------------------------------------------------------------
// Fold: Mf = dec_Wih @ out_W ; bf = dec_bih + dec_Wih @ out_b
// ---------------------------------------------------------------------------
__global__ void fold_kernel(const float* __restrict__ dWih, const float* __restrict__ outW,
                            const float* __restrict__ outb, const float* __restrict__ dbih) {
    int g = blockIdx.x, j = threadIdx.x;
    __shared__ float wrow[128];
    __shared__ float red[128];
    wrow[j] = dWih[g * 128 + j];
    __syncthreads();
    float acc = 0.0f;
#pragma unroll 8
    for (int f = 0; f < 128; f++) acc = fmaf(wrow[f], outW[f * 128 + j], acc);
    g_Mf[g * 128 + j] = acc;
    red[j] = wrow[j] * outb[j];
    __syncthreads();
    for (int s = 64; s > 0; s >>= 1) {
        if (j < s) red[j] += red[j + s];
        __syncthreads();
    }
    if (j == 0) g_bf[g] = dbih[g] + red[0];
}

// ---------------------------------------------------------------------------
// Encoder recurrence (scalar FMA, fast gates)
// ---------------------------------------------------------------------------
__global__ void __launch_bounds__(384, 1) enc_kernel(const float* __restrict__ Whh,
                                                     const float* __restrict__ bhh) {
    __shared__ float h_sm[2][128];
    __shared__ float gh_sm[2][384];
    int g = threadIdx.x;
    int b0 = blockIdx.x * 2;
    float w[128];
#pragma unroll
    for (int k = 0; k < 128; k += 4) {
        float4 v = *(const float4*)&Whh[(size_t)g * 128 + k];
        w[k] = v.x; w[k + 1] = v.y; w[k + 2] = v.z; w[k + 3] = v.w;
    }
    float bg = bhh[g];
    int bb = g >> 7, j = g & 127;
    if (g < 256) h_sm[bb][j] = 0.0f;
    __syncthreads();

    for (int t = 0; t < 512; t++) {
        float gi_r = 0.f, gi_z = 0.f, gi_n = 0.f;
        if (g < 256) {
            const float* gp = g_Genc + ((size_t)t * 256 + b0 + bb) * 384;
            gi_r = gp[j]; gi_z = gp[128 + j]; gi_n = gp[256 + j];
        }
        float a0 = bg, a1 = bg;
#pragma unroll
        for (int k = 0; k < 128; k += 4) {
            float4 h0 = *(const float4*)&h_sm[0][k];
            float4 h1 = *(const float4*)&h_sm[1][k];
            a0 = fmaf(w[k], h0.x, a0);     a1 = fmaf(w[k], h1.x, a1);
            a0 = fmaf(w[k + 1], h0.y, a0); a1 = fmaf(w[k + 1], h1.y, a1);
            a0 = fmaf(w[k + 2], h0.z, a0); a1 = fmaf(w[k + 2], h1.z, a1);
            a0 = fmaf(w[k + 3], h0.w, a0); a1 = fmaf(w[k + 3], h1.w, a1);
        }
        gh_sm[0][g] = a0;
        gh_sm[1][g] = a1;
        __syncthreads();
        if (g < 256) {
            float r = sigf(gi_r + gh_sm[bb][j]);
            float z = sigf(gi_z + gh_sm[bb][128 + j]);
            float n = tanh_fast(gi_n + r * gh_sm[bb][256 + j]);
            h_sm[bb][j] = (1.0f - z) * n + z * h_sm[bb][j];
        }
        __syncthreads();
    }
    if (g < 256) g_Henc[(b0 + bb) * 128 + j] = h_sm[bb][j];
}

// ---------------------------------------------------------------------------
// Decoder recurrence (R7 core; fast gates; writes h split DIRECTLY to
// g_Xh/g_Xl rows r=i*256+b — no fp32 trajectory, no conv_h pass).
// ---------------------------------------------------------------------------
__global__ void __launch_bounds__(384, 1) dec_kernel(const float* __restrict__ Whh,
                                                     const float* __restrict__ bhh) {
    extern __shared__ __align__(16) unsigned char dsm[];
    ulonglong2* wq = (ulonglong2*)dsm;                 // [32][384] -> 196608 B
    float* hsm = (float*)(dsm + 196608);
    float* gis = hsm + 256;
    float* ghs = gis + 768;
    int g = threadIdx.x;
    int b0 = blockIdx.x * 2;
    int bb = g >> 7, j = g & 127;

    ull w2[64];
    {
        const ull* wrow = (const ull*)g_Mf + (size_t)g * 64;
#pragma unroll
        for (int kp = 0; kp < 64; kp++) w2[kp] = wrow[kp];
    }
    float bfg = g_bf[g];
    float bhg = bhh[g];

    for (int idx = g; idx < 384 * 32; idx += 384) {
        int gg = idx >> 5, q = idx & 31;
        wq[q * 384 + gg] = ((const ulonglong2*)Whh)[(size_t)gg * 32 + q];
    }
    if (g < 256) {
        float h_init = g_Henc[b0 * 128 + g];
        hsm[g] = h_init;
        __nv_bfloat16 hh = __float2bfloat16(h_init);
        size_t row = ((size_t)0 * 256 + b0 + bb) * 128 + j;
        g_Xh[row] = hh;
        g_Xl[row] = __float2bfloat16(h_init - __bfloat162float(hh));
    }
    __syncthreads();

    for (int i = 0; i < 512; i++) {
        ull gi0 = pk2(bfg, 0.f), gi1 = pk2(bfg, 0.f);
        ull gh0 = pk2(bhg, 0.f), gh1 = pk2(bhg, 0.f);
#pragma unroll
        for (int grp = 0; grp < 16; grp++) {
            ulonglong2 wvA = wq[(2 * grp) * 384 + g];
            ulonglong2 wvB = wq[(2 * grp + 1) * 384 + g];
            ulonglong2 h0A = *(const ulonglong2*)&hsm[8 * grp];
            ulonglong2 h0B = *(const ulonglong2*)&hsm[8 * grp + 4];
            ulonglong2 h1A = *(const ulonglong2*)&hsm[128 + 8 * grp];
            ulonglong2 h1B = *(const ulonglong2*)&hsm[128 + 8 * grp + 4];
            gi0 = f2fma(w2[4 * grp],     h0A.x, gi0);
            gi1 = f2fma(w2[4 * grp],     h1A.x, gi1);
            gi0 = f2fma(w2[4 * grp + 1], h0A.y, gi0);
            gi1 = f2fma(w2[4 * grp + 1], h1A.y, gi1);
            gi0 = f2fma(w2[4 * grp + 2], h0B.x, gi0);
            gi1 = f2fma(w2[4 * grp + 2], h1B.x, gi1);
            gi0 = f2fma(w2[4 * grp + 3], h0B.y, gi0);
            gi1 = f2fma(w2[4 * grp + 3], h1B.y, gi1);
            gh0 = f2fma(wvA.x, h0A.x, gh0);
            gh1 = f2fma(wvA.x, h1A.x, gh1);
            gh0 = f2fma(wvA.y, h0A.y, gh0);
            gh1 = f2fma(wvA.y, h1A.y, gh1);
            gh0 = f2fma(wvB.x, h0B.x, gh0);
            gh1 = f2fma(wvB.x, h1B.x, gh1);
            gh0 = f2fma(wvB.y, h0B.y, gh0);
            gh1 = f2fma(wvB.y, h1B.y, gh1);
        }
        gis[g] = psum(gi0); gis[384 + g] = psum(gi1);
        ghs[g] = psum(gh0); ghs[384 + g] = psum(gh1);
        __syncthreads();
        if (g < 256) {
            int base = bb * 384;
            float r = sigf(gis[base + j] + ghs[base + j]);
            float z = sigf(gis[base + 128 + j] + ghs[base + 128 + j]);
            float n = tanh_fast(gis[base + 256 + j] + r * ghs[base + 256 + j]);
            float h_new = (1.0f - z) * n + z * hsm[g];
            hsm[g] = h_new;
            if (i < 511) {
                __nv_bfloat16 hh = __float2bfloat16(h_new);
                size_t row = ((size_t)(i + 1) * 256 + b0 + bb) * 128 + j;
                g_Xh[row] = hh;
                g_Xl[row] = __float2bfloat16(h_new - __bfloat162float(hh));
            }
        }
        __syncthreads();
    }
}

// ---------------------------------------------------------------------------
// Epilogues (unchanged; exact expf/tanhf kept here)
// ---------------------------------------------------------------------------
__device__ __forceinline__ float bsum(float v, float* red) {
    int t = threadIdx.x;
    __syncthreads();
    red[t] = v;
    __syncthreads();
    for (int s = 128; s > 0; s >>= 1) {
        if (t < s) red[t] += red[t + s];
        __syncthreads();
    }
    return red[0];
}

__global__ void __launch_bounds__(256) epiA(
    const float* __restrict__ X,
    const float* __restrict__ protos,
    const float* __restrict__ lnzw, const float* __restrict__ lnzb,
    const float* __restrict__ lnpw, const float* __restrict__ lnpb,
    const float* __restrict__ lnaw, const float* __restrict__ lnab,
    const float* __restrict__ beta,
    const float* __restrict__ e1W, const float* __restrict__ e1b,
    const float* __restrict__ e2W, const float* __restrict__ e2b,
    float* __restrict__ out) {
    int b = blockIdx.x, t = threadIdx.x;
    __shared__ float red[256];
    __shared__ float zln[128];
    __shared__ float pl[8][128];
    __shared__ float dotk[8];
    __shared__ float attnv[8];
    __shared__ float zfull[129];
    __shared__ float h1s[10];
    __shared__ float lg[4];

    const float* a = X + (size_t)b * 65536;
    const float* o = out + OFF_OUT + (size_t)b * 65536;
    float sab = 0.f, saa = 0.f, sbb = 0.f;
    for (int i = t; i < 65536; i += 256) {
        float av = a[i], bv = o[i];
        sab = fmaf(av, bv, sab);
        saa = fmaf(av, av, saa);
        sbb = fmaf(bv, bv, sbb);
    }
    sab = bsum(sab, red);
    saa = bsum(saa, red);
    sbb = bsum(sbb, red);
    float rc = sab / (fmaxf(sqrtf(saa), 1e-8f) * fmaxf(sqrtf(sbb), 1e-8f));

    float h = (t < 128) ? g_Henc[b * 128 + t] : 0.0f;
    if (t < 128) out[OFF_HENC + b * 128 + t] = h;
    float mu = bsum(h, red) * (1.0f / 128.0f);
    float d = (t < 128) ? (h - mu) : 0.0f;
    float var = bsum(d * d, red) * (1.0f / 128.0f);
    if (t < 128) zln[t] = lnzw[t] * d * rsqrtf(var + 1e-12f) + lnzb[t];

    for (int k = 0; k < 8; k++) {
        float p = (t < 128) ? protos[k * 128 + t] : 0.0f;
        float pu = bsum(p, red) * (1.0f / 128.0f);
        float pd = (t < 128) ? (p - pu) : 0.0f;
        float pv = bsum(pd * pd, red) * (1.0f / 128.0f);
        if (t < 128) pl[k][t] = lnpw[t] * pd * rsqrtf(pv + 1e-12f) + lnpb[t];
    }
    __syncthreads();

    for (int k = 0; k < 8; k++) {
        float pp = (t < 128) ? zln[t] * pl[k][t] : 0.0f;
        float s = bsum(pp, red);
        if (t == 0) dotk[k] = s * 0.08838834764831845f;
    }
    __syncthreads();
    if (t < 8) {
        float m = -1e30f;
        for (int kk = 0; kk < 8; kk++) m = fmaxf(m, dotk[kk]);
        float s = 0.f;
        for (int kk = 0; kk < 8; kk++) s += expf(dotk[kk] - m);
        attnv[t] = expf(dotk[t] - m) / s;
    }
    __syncthreads();

    float zacc = 0.0f;
    for (int k = 0; k < 8; k++) {
        float v = (t < 128) ? (beta[k * 128 + t] + attnv[k] * h) : 0.0f;
        float vu = bsum(v, red) * (1.0f / 128.0f);
        float vd = (t < 128) ? (v - vu) : 0.0f;
        float vv = bsum(vd * vd, red) * (1.0f / 128.0f);
        if (t < 128) {
            float dval = lnaw[t] * vd * rsqrtf(vv + 1e-12f) + lnab[t];
            out[OFF_DIS + ((size_t)b * 8 + k) * 128 + t] = dval;
            zacc += dval;
        }
    }
    if (t < 128) {
        float zv = zacc * 0.125f;
        zfull[t] = zv;
        out[OFF_Z + (size_t)b * 129 + t] = zv;
    }
    if (t == 0) {
        zfull[128] = rc;
        out[OFF_Z + (size_t)b * 129 + 128] = rc;
    }
    __syncthreads();

    if (t < 10) {
        float acc = e1b[t];
        for (int i = 0; i < 129; i++) acc = fmaf(e1W[t * 129 + i], zfull[i], acc);
        h1s[t] = tanhf(acc);
    }
    __syncthreads();
    if (t < 4) {
        float acc = e2b[t];
        for (int i = 0; i < 10; i++) acc = fmaf(e2W[t * 10 + i], h1s[i], acc);
        lg[t] = acc;
    }
    __syncthreads();
    if (t < 4) {
        float m = fmaxf(fmaxf(lg[0], lg[1]), fmaxf(lg[2], lg[3]));
        float s = expf(lg[0] - m) + expf(lg[1] - m) + expf(lg[2] - m) + expf(lg[3] - m);
        out[OFF_GAMMA + (size_t)b * 4 + t] = expf(lg[t] - m) / s;
    }
}

__global__ void epiB(float* __restrict__ out, const int* __restrict__ perm) {
    int b = blockIdx.x;
    for (int e = threadIdx.x; e < 1024; e += blockDim.x) {
        int k = e >> 7, j = e & 127;
        int src = perm[k * 256 + b];
        out[OFF_DISP + ((size_t)b * 8 + k) * 128 + j] =
            out[OFF_DIS + ((size_t)src * 8 + k) * 128 + j];
    }
}

// ---------------------------------------------------------------------------
extern "C" void kernel_launch(void* const* d_in, const int* in_sizes, int n_in,
                              void* d_out, int out_size) {
    const float* input   = (const float*)d_in[0];
    const float* enc_Wih = (const float*)d_in[1];
    const float* enc_Whh = (const float*)d_in[2];
    const float* enc_bih = (const float*)d_in[3];
    const float* enc_bhh = (const float*)d_in[4];
    const float* dec_Wih = (const float*)d_in[5];
    const float* dec_Whh = (const float*)d_in[6];
    const float* dec_bih = (const float*)d_in[7];
    const float* dec_bhh = (const float*)d_in[8];
    const float* out_W   = (const float*)d_in[9];
    const float* out_b   = (const float*)d_in[10];
    const float* protos  = (const float*)d_in[11];
    const float* lnz_w   = (const float*)d_in[12];
    const float* lnz_b   = (const float*)d_in[13];
    const float* lnp_w   = (const float*)d_in[14];
    const float* lnp_b   = (const float*)d_in[15];
    const float* lna_w   = (const float*)d_in[16];
    const float* lna_b   = (const float*)d_in[17];
    const float* beta    = (const float*)d_in[18];
    const float* est1_W  = (const float*)d_in[19];
    const float* est1_b  = (const float*)d_in[20];
    const float* est2_W  = (const float*)d_in[21];
    const float* est2_b  = (const float*)d_in[22];
    float* out = (float*)d_out;

    int* perm_ptr = nullptr;
    cudaGetSymbolAddress((void**)&perm_ptr, g_perm);

    cudaFuncSetAttribute(dec_kernel, cudaFuncAttributeMaxDynamicSharedMemorySize, 204288);
    cudaFuncSetAttribute(mma_gemm_gi, cudaFuncAttributeMaxDynamicSharedMemorySize, MMA_SMEM);
    cudaFuncSetAttribute(mma_gemm_out, cudaFuncAttributeMaxDynamicSharedMemorySize, MMA_SMEM);

    // 1. bf16 split conversion of X, enc_Wih, out_W
    conv_x<<<8192, 256>>>(input);
    conv_w<<<24, 256>>>(enc_Wih);
    conv_ow<<<8, 256>>>(out_W);
    // 2. Tensor-core gi GEMM (split-bf16, 3 terms)
    mma_gemm_gi<<<dim3(3, 1024), 256, MMA_SMEM>>>(enc_bih);
    // 3. Encoder recurrence (fast gates)
    enc_kernel<<<128, 384>>>(enc_Whh, enc_bhh);
    // 4. Fold output projection into decoder input weights
    fold_kernel<<<384, 128>>>(dec_Wih, out_W, out_b, dec_bih);
    // 5. Decoder recurrence (fast gates, writes bf16 h split directly)
    dec_kernel<<<128, 384, 204288>>>(dec_Whh, dec_bhh);
    // 6. Tensor-core out GEMM (A = h split written by dec)
    mma_gemm_out<<<1024, 256, MMA_SMEM>>>(out_b, out);
    // 7. JAX-exact permutations
    perm_kernel<<<1, 256>>>(perm_ptr);
    // 8. Epilogue
    epiA<<<256, 256>>>(input, protos, lnz_w, lnz_b, lnp_w, lnp_b, lna_w, lna_b,
                       beta, est1_W, est1_b, est2_W, est2_b, out);
    // 9. dis_perm gather
    epiB<<<256, 256>>>(out, perm_ptr);
}

// round 15
// speedup vs baseline: 1.1088x; 1.0424x over previous
#include <cuda_runtime.h>
#include <cuda_bf16.h>
#include <math.h>
#include <stdint.h>
#include <stddef.h>

// Problem dims
#define Bsz 256
#define Ssz 512
#define Fdim 128
#define Hdim 128
#define G3  384   // 3*H

// Output layout (tuple flattened): h_enc, output, z, gamma, dis, dis_perm
#define OFF_HENC  ((size_t)0)
#define OFF_OUT   ((size_t)32768)                       // 256*128
#define OFF_Z     ((size_t)(32768 + 16777216))          // + 256*512*128
#define OFF_GAMMA ((size_t)(OFF_Z + 256*129))
#define OFF_DIS   ((size_t)(OFF_GAMMA + 256*4))
#define OFF_DISP  ((size_t)(OFF_DIS + 256*8*128))

typedef unsigned long long ull;

// Scratch (device globals; no allocations allowed)
__device__ float g_Genc[(size_t)Ssz * Bsz * G3];    // [t][b][g]  192 MB
__device__ float g_Henc[Bsz * Hdim];
__device__ float g_Mf[G3 * Hdim];
__device__ float g_bf[G3];
__device__ int   g_perm[8 * Bsz];
// bf16 split h-trajectory written by the decoder for the out GEMM.
__device__ __nv_bfloat16 g_Xh[(size_t)131072 * 128];   // 33.5 MB
__device__ __nv_bfloat16 g_Xl[(size_t)131072 * 128];
__device__ __nv_bfloat16 g_Wh[G3 * 128];
__device__ __nv_bfloat16 g_Wl[G3 * 128];
__device__ __nv_bfloat16 g_Oh[128 * 128];              // out_W split
__device__ __nv_bfloat16 g_Ol[128 * 128];

// Fast gate math: __expf is a single MUFU.EX2-based approx (~2 ulp).
__device__ __forceinline__ float sigf(float x) { return 1.0f / (1.0f + __expf(-x)); }
__device__ __forceinline__ float tanh_fast(float x) {
    float t = __expf(-2.0f * fabsf(x));      // in (0,1], no overflow
    float r = (1.0f - t) / (1.0f + t);
    return copysignf(r, x);
}

// ---- packed f32x2 helpers (used by dec only) ----
__device__ __forceinline__ ull pk2(float lo, float hi) {
    ull r; asm("mov.b64 %0, {%1, %2};" : "=l"(r) : "f"(lo), "f"(hi)); return r;
}
__device__ __forceinline__ ull f2fma(ull a, ull b, ull c) {
    ull d; asm("fma.rn.f32x2 %0, %1, %2, %3;" : "=l"(d) : "l"(a), "l"(b), "l"(c)); return d;
}
__device__ __forceinline__ float psum(ull v) {
    float a, b; asm("mov.b64 {%0, %1}, %2;" : "=f"(a), "=f"(b) : "l"(v)); return a + b;
}

__device__ __forceinline__ unsigned smaddr(const void* p) {
    unsigned a;
    asm("{ .reg .u64 t; cvta.to.shared.u64 t, %1; cvt.u32.u64 %0, t; }" : "=r"(a) : "l"(p));
    return a;
}

__device__ __forceinline__ void ldsm4(unsigned* f, unsigned addr) {
    asm volatile("ldmatrix.sync.aligned.m8n8.x4.shared.b16 {%0,%1,%2,%3}, [%4];"
                 : "=r"(f[0]), "=r"(f[1]), "=r"(f[2]), "=r"(f[3]) : "r"(addr));
}
__device__ __forceinline__ void mma16816(float* d, const unsigned* a, unsigned b0, unsigned b1) {
    asm volatile(
        "mma.sync.aligned.m16n8k16.row.col.f32.bf16.bf16.f32 "
        "{%0,%1,%2,%3}, {%4,%5,%6,%7}, {%8,%9}, {%0,%1,%2,%3};"
        : "+f"(d[0]), "+f"(d[1]), "+f"(d[2]), "+f"(d[3])
        : "r"(a[0]), "r"(a[1]), "r"(a[2]), "r"(a[3]), "r"(b0), "r"(b1));
}

// ---------------------------------------------------------------------------
// Threefry2x32 (exact JAX constants)
// ---------------------------------------------------------------------------
__device__ __forceinline__ uint2 threefry(unsigned k0, unsigned k1,
                                          unsigned x0, unsigned x1) {
    unsigned ks2 = k0 ^ k1 ^ 0x1BD11BDAu;
    x0 += k0; x1 += k1;
#define TFR(r) { x0 += x1; x1 = (x1 << (r)) | (x1 >> (32 - (r))); x1 ^= x0; }
    TFR(13) TFR(15) TFR(26) TFR(6)   x0 += k1;  x1 += ks2 + 1u;
    TFR(17) TFR(29) TFR(16) TFR(24)  x0 += ks2; x1 += k0 + 2u;
    TFR(13) TFR(15) TFR(26) TFR(6)   x0 += k0;  x1 += k1 + 3u;
    TFR(17) TFR(29) TFR(16) TFR(24)  x0 += k1;  x1 += ks2 + 4u;
    TFR(13) TFR(15) TFR(26) TFR(6)   x0 += ks2; x1 += k0 + 5u;
#undef TFR
    return make_uint2(x0, x1);
}

__global__ void perm_kernel(int* __restrict__ perm) {
    __shared__ unsigned sk[8][2];
    __shared__ unsigned bits[256];
    int t = threadIdx.x;
    if (t < 8) {
        uint2 pk = threefry(0u, 42u, 0u, (unsigned)t);
        uint2 s  = threefry(pk.x, pk.y, 0u, 1u);
        sk[t][0] = s.x; sk[t][1] = s.y;
    }
    __syncthreads();
    for (int k = 0; k < 8; k++) {
        uint2 y = threefry(sk[k][0], sk[k][1], 0u, (unsigned)t);
        bits[t] = y.x ^ y.y;
        __syncthreads();
        unsigned mine = bits[t];
        int rank = 0;
        for (int j = 0; j < 256; j++) {
            unsigned o = bits[j];
            rank += (o < mine) || (o == mine && j < t);
        }
        perm[k * 256 + rank] = t;
        __syncthreads();
    }
}

// ---------------------------------------------------------------------------
// bf16 split conversions (weights only; X is split inside mma_gemm_gi)
// ---------------------------------------------------------------------------
__global__ void conv_w(const float* __restrict__ W) {
    unsigned c = blockIdx.x * blockDim.x + threadIdx.x;
    int k0 = (c & 15) * 8;
    int gt = (int)(c >> 4);
    const float* src = W + ((size_t)gt * 128 + k0);
    size_t dst = (size_t)gt * 128 + k0;
#pragma unroll
    for (int i = 0; i < 8; i++) {
        float x = src[i];
        __nv_bfloat16 h = __float2bfloat16(x);
        g_Wh[dst + i] = h;
        g_Wl[dst + i] = __float2bfloat16(x - __bfloat162float(h));
    }
}

__global__ void conv_ow(const float* __restrict__ W) {
    unsigned c = blockIdx.x * blockDim.x + threadIdx.x;
    size_t base = (size_t)c * 8;
#pragma unroll
    for (int i = 0; i < 8; i++) {
        float x = W[base + i];
        __nv_bfloat16 h = __float2bfloat16(x);
        g_Oh[base + i] = h;
        g_Ol[base + i] = __float2bfloat16(x - __bfloat162float(h));
    }
}

// ---------------------------------------------------------------------------
// HMMA gi GEMM (split-bf16, 3 terms): g_Genc[r][g] = x[r,:].W[g,:] + bias
// A is loaded from X (fp32) and split to bf16 hi/lo in-kernel — no conv_x.
// ---------------------------------------------------------------------------
#define APAD 136
#define MMA_SMEM (4 * 128 * APAD * 2)   // 139264 B

__global__ void __launch_bounds__(256) mma_gemm_gi(const float* __restrict__ X,
                                                   const float* __restrict__ bias) {
    extern __shared__ __align__(16) __nv_bfloat16 sm[];
    __nv_bfloat16* sAh = sm;
    __nv_bfloat16* sAl = sm + 128 * APAD;
    __nv_bfloat16* sBh = sm + 2 * 128 * APAD;
    __nv_bfloat16* sBl = sm + 3 * 128 * APAD;
    __shared__ float bias_s[128];
    int tid = threadIdx.x;
    int wid = tid >> 5, lane = tid & 31;
    int n0 = blockIdx.x * 128;
    size_t rBase = (size_t)blockIdx.y * 128;

    if (tid < 128) bias_s[tid] = bias[n0 + tid];

    // Load A from fp32 X with on-the-fly hi/lo bf16 split.
    // r = t*256 + b  ->  X[b][t][k]
#pragma unroll
    for (int i = 0; i < 8; i++) {
        int c = tid + i * 256;
        int r = c >> 4, k0 = (c & 15) * 8;
        size_t R = rBase + r;
        int bb = (int)(R & 255), tt = (int)(R >> 8);
        const float* xp = X + (((size_t)bb * 512 + tt) * 128 + k0);
        float4 xa = *(const float4*)xp;
        float4 xb = *(const float4*)(xp + 4);
        float xs[8] = {xa.x, xa.y, xa.z, xa.w, xb.x, xb.y, xb.z, xb.w};
        __nv_bfloat16 hb[8], lb[8];
#pragma unroll
        for (int e = 0; e < 8; e++) {
            __nv_bfloat16 h = __float2bfloat16(xs[e]);
            hb[e] = h;
            lb[e] = __float2bfloat16(xs[e] - __bfloat162float(h));
        }
        *(uint4*)&sAh[r * APAD + k0] = *(uint4*)hb;
        *(uint4*)&sAl[r * APAD + k0] = *(uint4*)lb;
    }
#pragma unroll
    for (int i = 0; i < 8; i++) {
        int c = tid + i * 256;
        int r = c >> 4, k0 = (c & 15) * 8;
        uint4 vh = *(const uint4*)&g_Wh[(size_t)(n0 + r) * 128 + k0];
        uint4 vl = *(const uint4*)&g_Wl[(size_t)(n0 + r) * 128 + k0];
        *(uint4*)&sBh[r * APAD + k0] = vh;
        *(uint4*)&sBl[r * APAD + k0] = vl;
    }
    __syncthreads();

    int wm = wid >> 1, wn = wid & 1;
    float d[2][8][4];
#pragma unroll
    for (int mf = 0; mf < 2; mf++)
#pragma unroll
        for (int nf = 0; nf < 8; nf++)
#pragma unroll
            for (int e = 0; e < 4; e++) d[mf][nf][e] = 0.0f;

    int aRow = wm * 32 + (lane & 7) + ((lane >> 3) & 1) * 8;
    int aCol = (lane >> 4) * 8;
    int bRow = wn * 64 + (lane & 7) + ((lane >= 16) ? 8 : 0);
    int bCol = ((lane >> 3) & 1) * 8;

    for (int ks = 0; ks < 8; ks++) {
        int k0 = ks * 16;
        unsigned ah[2][4], al[2][4];
#pragma unroll
        for (int mf = 0; mf < 2; mf++) {
            unsigned off = (unsigned)((aRow + mf * 16) * APAD + k0 + aCol) * 2u;
            ldsm4(ah[mf], smaddr(sAh) + off);
            ldsm4(al[mf], smaddr(sAl) + off);
        }
#pragma unroll
        for (int np = 0; np < 4; np++) {
            unsigned off = (unsigned)((bRow + np * 16) * APAD + k0 + bCol) * 2u;
            unsigned bh[4], bl[4];
            ldsm4(bh, smaddr(sBh) + off);
            ldsm4(bl, smaddr(sBl) + off);
#pragma unroll
            for (int mf = 0; mf < 2; mf++) {
                mma16816(d[mf][np * 2],     ah[mf], bh[0], bh[1]);
                mma16816(d[mf][np * 2 + 1], ah[mf], bh[2], bh[3]);
                mma16816(d[mf][np * 2],     ah[mf], bl[0], bl[1]);
                mma16816(d[mf][np * 2 + 1], ah[mf], bl[2], bl[3]);
                mma16816(d[mf][np * 2],     al[mf], bh[0], bh[1]);
                mma16816(d[mf][np * 2 + 1], al[mf], bh[2], bh[3]);
            }
        }
    }

    int group = lane >> 2, tg = lane & 3;
#pragma unroll
    for (int mf = 0; mf < 2; mf++) {
#pragma unroll
        for (int nf = 0; nf < 8; nf++) {
            int row = wm * 32 + mf * 16 + group;
            int col = wn * 64 + nf * 8 + tg * 2;
            size_t r = rBase + row;
            float b0 = bias_s[col], b1 = bias_s[col + 1];
            float2 v0 = make_float2(d[mf][nf][0] + b0, d[mf][nf][1] + b1);
            float2 v1 = make_float2(d[mf][nf][2] + b0, d[mf][nf][3] + b1);
            *(float2*)&g_Genc[r * 384 + n0 + col] = v0;
            *(float2*)&g_Genc[(r + 8) * 384 + n0 + col] = v1;
        }
    }
}

// ---------------------------------------------------------------------------
// HMMA out GEMM (split-bf16): o[r][f] = h[r,:].out_W[f,:] + out_b[f]
// A = g_Xh/g_Xl (decoder h-trajectory split). B = g_Oh/g_Ol.
// ---------------------------------------------------------------------------
__global__ void __launch_bounds__(256) mma_gemm_out(const float* __restrict__ bias,
                                                    float* __restrict__ out) {
    extern __shared__ __align__(16) __nv_bfloat16 sm[];
    __nv_bfloat16* sAh = sm;
    __nv_bfloat16* sAl = sm + 128 * APAD;
    __nv_bfloat16* sBh = sm + 2 * 128 * APAD;
    __nv_bfloat16* sBl = sm + 3 * 128 * APAD;
    __shared__ float bias_s[128];
    int tid = threadIdx.x;
    int wid = tid >> 5, lane = tid & 31;
    size_t rBase = (size_t)blockIdx.x * 128;

    if (tid < 128) bias_s[tid] = bias[tid];

#pragma unroll
    for (int i = 0; i < 8; i++) {
        int c = tid + i * 256;
        int r = c >> 4, k0 = (c & 15) * 8;
        uint4 vh = *(const uint4*)&g_Xh[(rBase + r) * 128 + k0];
        uint4 vl = *(const uint4*)&g_Xl[(rBase + r) * 128 + k0];
        *(uint4*)&sAh[r * APAD + k0] = vh;
        *(uint4*)&sAl[r * APAD + k0] = vl;
    }
#pragma unroll
    for (int i = 0; i < 8; i++) {
        int c = tid + i * 256;
        int r = c >> 4, k0 = (c & 15) * 8;
        uint4 vh = *(const uint4*)&g_Oh[(size_t)r * 128 + k0];
        uint4 vl = *(const uint4*)&g_Ol[(size_t)r * 128 + k0];
        *(uint4*)&sBh[r * APAD + k0] = vh;
        *(uint4*)&sBl[r * APAD + k0] = vl;
    }
    __syncthreads();

    int wm = wid >> 1, wn = wid & 1;
    float d[2][8][4];
#pragma unroll
    for (int mf = 0; mf < 2; mf++)
#pragma unroll
        for (int nf = 0; nf < 8; nf++)
#pragma unroll
            for (int e = 0; e < 4; e++) d[mf][nf][e] = 0.0f;

    int aRow = wm * 32 + (lane & 7) + ((lane >> 3) & 1) * 8;
    int aCol = (lane >> 4) * 8;
    int bRow = wn * 64 + (lane & 7) + ((lane >= 16) ? 8 : 0);
    int bCol = ((lane >> 3) & 1) * 8;

    for (int ks = 0; ks < 8; ks++) {
        int k0 = ks * 16;
        unsigned ah[2][4], al[2][4];
#pragma unroll
        for (int mf = 0; mf < 2; mf++) {
            unsigned off = (unsigned)((aRow + mf * 16) * APAD + k0 + aCol) * 2u;
            ldsm4(ah[mf], smaddr(sAh) + off);
            ldsm4(al[mf], smaddr(sAl) + off);
        }
#pragma unroll
        for (int np = 0; np < 4; np++) {
            unsigned off = (unsigned)((bRow + np * 16) * APAD + k0 + bCol) * 2u;
            unsigned bh[4], bl[4];
            ldsm4(bh, smaddr(sBh) + off);
            ldsm4(bl, smaddr(sBl) + off);
#pragma unroll
            for (int mf = 0; mf < 2; mf++) {
                mma16816(d[mf][np * 2],     ah[mf], bh[0], bh[1]);
                mma16816(d[mf][np * 2 + 1], ah[mf], bh[2], bh[3]);
                mma16816(d[mf][np * 2],     ah[mf], bl[0], bl[1]);
                mma16816(d[mf][np * 2 + 1], ah[mf], bl[2], bl[3]);
                mma16816(d[mf][np * 2],     al[mf], bh[0], bh[1]);
                mma16816(d[mf][np * 2 + 1], al[mf], bh[2], bh[3]);
            }
        }
    }

    // Epilogue with time reversal: r = i*256+b -> output[b][511-i][:]
    int group = lane >> 2, tg = lane & 3;
#pragma unroll
    for (int mf = 0; mf < 2; mf++) {
#pragma unroll
        for (int nf = 0; nf < 8; nf++) {
            int row = wm * 32 + mf * 16 + group;
            int col = wn * 64 + nf * 8 + tg * 2;
            float b0 = bias_s[col], b1 = bias_s[col + 1];
            size_t r0 = rBase + row;
            size_t r1 = r0 + 8;
            int is0 = (int)(r0 >> 8), bb0 = (int)(r0 & 255);
            int is1 = (int)(r1 >> 8), bb1 = (int)(r1 & 255);
            size_t o0 = (size_t)(bb0 * 512 + (511 - is0)) * 128;
            size_t o1 = (size_t)(bb1 * 512 + (511 - is1)) * 128;
            float2 v0 = make_float2(d[mf][nf][0] + b0, d[mf][nf][1] + b1);
            float2 v1 = make_float2(d[mf][nf][2] + b0, d[mf][nf][3] + b1);
            *(float2*)&out[OFF_OUT + o0 + col] = v0;
            *(float2*)&out[OFF_OUT + o1 + col] = v1;
        }
    }
}

// ---------------------------------------------------------------------------
// Fold: Mf = dec_Wih @ out_W ; bf = dec_bih + dec_Wih @ out_b
// ---------------------------------------------------------------------------
__global__ void fold_kernel(const float* __restrict__ dWih, const float* __restrict__ outW,
                            const float* __restrict__ outb, const float* __restrict__ dbih) {
    int g = blockIdx.x, j = threadIdx.x;
    __shared__ float wrow[128];
    __shared__ float red[128];
    wrow[j] = dWih[g * 128 + j];
    __syncthreads();
    float acc = 0.0f;
#pragma unroll 8
    for (int f = 0; f < 128; f++) acc = fmaf(wrow[f], outW[f * 128 + j], acc);
    g_Mf[g * 128 + j] = acc;
    red[j] = wrow[j] * outb[j];
    __syncthreads();
    for (int s = 64; s > 0; s >>= 1) {
        if (j < s) red[j] += red[j + s];
        __syncthreads();
    }
    if (j == 0) g_bf[g] = dbih[g] + red[0];
}

// ---------------------------------------------------------------------------
// Encoder recurrence (scalar FMA, fast gates)
// ---------------------------------------------------------------------------
__global__ void __launch_bounds__(384, 1) enc_kernel(const float* __restrict__ Whh,
                                                     const float* __restrict__ bhh) {
    __shared__ float h_sm[2][128];
    __shared__ float gh_sm[2][384];
    int g = threadIdx.x;
    int b0 = blockIdx.x * 2;
    float w[128];
#pragma unroll
    for (int k = 0; k < 128; k += 4) {
        float4 v = *(const float4*)&Whh[(size_t)g * 128 + k];
        w[k] = v.x; w[k + 1] = v.y; w[k + 2] = v.z; w[k + 3] = v.w;
    }
    float bg = bhh[g];
    int bb = g >> 7, j = g & 127;
    if (g < 256) h_sm[bb][j] = 0.0f;
    __syncthreads();

    for (int t = 0; t < 512; t++) {
        float gi_r = 0.f, gi_z = 0.f, gi_n = 0.f;
        if (g < 256) {
            const float* gp = g_Genc + ((size_t)t * 256 + b0 + bb) * 384;
            gi_r = gp[j]; gi_z = gp[128 + j]; gi_n = gp[256 + j];
        }
        float a0 = bg, a1 = bg;
#pragma unroll
        for (int k = 0; k < 128; k += 4) {
            float4 h0 = *(const float4*)&h_sm[0][k];
            float4 h1 = *(const float4*)&h_sm[1][k];
            a0 = fmaf(w[k], h0.x, a0);     a1 = fmaf(w[k], h1.x, a1);
            a0 = fmaf(w[k + 1], h0.y, a0); a1 = fmaf(w[k + 1], h1.y, a1);
            a0 = fmaf(w[k + 2], h0.z, a0); a1 = fmaf(w[k + 2], h1.z, a1);
            a0 = fmaf(w[k + 3], h0.w, a0); a1 = fmaf(w[k + 3], h1.w, a1);
        }
        gh_sm[0][g] = a0;
        gh_sm[1][g] = a1;
        __syncthreads();
        if (g < 256) {
            float r = sigf(gi_r + gh_sm[bb][j]);
            float z = sigf(gi_z + gh_sm[bb][128 + j]);
            float n = tanh_fast(gi_n + r * gh_sm[bb][256 + j]);
            h_sm[bb][j] = (1.0f - z) * n + z * h_sm[bb][j];
        }
        __syncthreads();
    }
    if (g < 256) g_Henc[(b0 + bb) * 128 + j] = h_sm[bb][j];
}

// ---------------------------------------------------------------------------
// Decoder recurrence (R7 core; fast gates; writes h split DIRECTLY to
// g_Xh/g_Xl rows r=i*256+b).
// ---------------------------------------------------------------------------
__global__ void __launch_bounds__(384, 1) dec_kernel(const float* __restrict__ Whh,
                                                     const float* __restrict__ bhh) {
    extern __shared__ __align__(16) unsigned char dsm[];
    ulonglong2* wq = (ulonglong2*)dsm;                 // [32][384] -> 196608 B
    float* hsm = (float*)(dsm + 196608);
    float* gis = hsm + 256;
    float* ghs = gis + 768;
    int g = threadIdx.x;
    int b0 = blockIdx.x * 2;
    int bb = g >> 7, j = g & 127;

    ull w2[64];
    {
        const ull* wrow = (const ull*)g_Mf + (size_t)g * 64;
#pragma unroll
        for (int kp = 0; kp < 64; kp++) w2[kp] = wrow[kp];
    }
    float bfg = g_bf[g];
    float bhg = bhh[g];

    for (int idx = g; idx < 384 * 32; idx += 384) {
        int gg = idx >> 5, q = idx & 31;
        wq[q * 384 + gg] = ((const ulonglong2*)Whh)[(size_t)gg * 32 + q];
    }
    if (g < 256) {
        float h_init = g_Henc[b0 * 128 + g];
        hsm[g] = h_init;
        __nv_bfloat16 hh = __float2bfloat16(h_init);
        size_t row = ((size_t)0 * 256 + b0 + bb) * 128 + j;
        g_Xh[row] = hh;
        g_Xl[row] = __float2bfloat16(h_init - __bfloat162float(hh));
    }
    __syncthreads();

    for (int i = 0; i < 512; i++) {
        ull gi0 = pk2(bfg, 0.f), gi1 = pk2(bfg, 0.f);
        ull gh0 = pk2(bhg, 0.f), gh1 = pk2(bhg, 0.f);
#pragma unroll
        for (int grp = 0; grp < 16; grp++) {
            ulonglong2 wvA = wq[(2 * grp) * 384 + g];
            ulonglong2 wvB = wq[(2 * grp + 1) * 384 + g];
            ulonglong2 h0A = *(const ulonglong2*)&hsm[8 * grp];
            ulonglong2 h0B = *(const ulonglong2*)&hsm[8 * grp + 4];
            ulonglong2 h1A = *(const ulonglong2*)&hsm[128 + 8 * grp];
            ulonglong2 h1B = *(const ulonglong2*)&hsm[128 + 8 * grp + 4];
            gi0 = f2fma(w2[4 * grp],     h0A.x, gi0);
            gi1 = f2fma(w2[4 * grp],     h1A.x, gi1);
            gi0 = f2fma(w2[4 * grp + 1], h0A.y, gi0);
            gi1 = f2fma(w2[4 * grp + 1], h1A.y, gi1);
            gi0 = f2fma(w2[4 * grp + 2], h0B.x, gi0);
            gi1 = f2fma(w2[4 * grp + 2], h1B.x, gi1);
            gi0 = f2fma(w2[4 * grp + 3], h0B.y, gi0);
            gi1 = f2fma(w2[4 * grp + 3], h1B.y, gi1);
            gh0 = f2fma(wvA.x, h0A.x, gh0);
            gh1 = f2fma(wvA.x, h1A.x, gh1);
            gh0 = f2fma(wvA.y, h0A.y, gh0);
            gh1 = f2fma(wvA.y, h1A.y, gh1);
            gh0 = f2fma(wvB.x, h0B.x, gh0);
            gh1 = f2fma(wvB.x, h1B.x, gh1);
            gh0 = f2fma(wvB.y, h0B.y, gh0);
            gh1 = f2fma(wvB.y, h1B.y, gh1);
        }
        gis[g] = psum(gi0); gis[384 + g] = psum(gi1);
        ghs[g] = psum(gh0); ghs[384 + g] = psum(gh1);
        __syncthreads();
        if (g < 256) {
            int base = bb * 384;
            float r = sigf(gis[base + j] + ghs[base + j]);
            float z = sigf(gis[base + 128 + j] + ghs[base + 128 + j]);
            float n = tanh_fast(gis[base + 256 + j] + r * ghs[base + 256 + j]);
            float h_new = (1.0f - z) * n + z * hsm[g];
            hsm[g] = h_new;
            if (i < 511) {
                __nv_bfloat16 hh = __float2bfloat16(h_new);
                size_t row = ((size_t)(i + 1) * 256 + b0 + bb) * 128 + j;
                g_Xh[row] = hh;
                g_Xl[row] = __float2bfloat16(h_new - __bfloat162float(hh));
            }
        }
        __syncthreads();
    }
}

// ---------------------------------------------------------------------------
// Epilogues. bsum now uses warp shuffles (2 syncs per call vs 10).
// ---------------------------------------------------------------------------
__device__ __forceinline__ float bsum(float v, float* red) {
    __syncthreads();   // protect red reuse from previous call
#pragma unroll
    for (int o = 16; o > 0; o >>= 1)
        v += __shfl_xor_sync(0xffffffffu, v, o);
    if ((threadIdx.x & 31) == 0) red[threadIdx.x >> 5] = v;
    __syncthreads();
    float s = red[0];
#pragma unroll
    for (int w = 1; w < 8; w++) s += red[w];
    return s;
}

__global__ void __launch_bounds__(256) epiA(
    const float* __restrict__ X,
    const float* __restrict__ protos,
    const float* __restrict__ lnzw, const float* __restrict__ lnzb,
    const float* __restrict__ lnpw, const float* __restrict__ lnpb,
    const float* __restrict__ lnaw, const float* __restrict__ lnab,
    const float* __restrict__ beta,
    const float* __restrict__ e1W, const float* __restrict__ e1b,
    const float* __restrict__ e2W, const float* __restrict__ e2b,
    float* __restrict__ out) {
    int b = blockIdx.x, t = threadIdx.x;
    __shared__ float red[8];
    __shared__ float zln[128];
    __shared__ float pl[8][128];
    __shared__ float dotk[8];
    __shared__ float attnv[8];
    __shared__ float zfull[129];
    __shared__ float h1s[10];
    __shared__ float lg[4];

    const float* a = X + (size_t)b * 65536;
    const float* o = out + OFF_OUT + (size_t)b * 65536;
    float sab = 0.f, saa = 0.f, sbb = 0.f;
    for (int i = t; i < 65536; i += 256) {
        float av = a[i], bv = o[i];
        sab = fmaf(av, bv, sab);
        saa = fmaf(av, av, saa);
        sbb = fmaf(bv, bv, sbb);
    }
    sab = bsum(sab, red);
    saa = bsum(saa, red);
    sbb = bsum(sbb, red);
    float rc = sab / (fmaxf(sqrtf(saa), 1e-8f) * fmaxf(sqrtf(sbb), 1e-8f));

    float h = (t < 128) ? g_Henc[b * 128 + t] : 0.0f;
    if (t < 128) out[OFF_HENC + b * 128 + t] = h;
    float mu = bsum(h, red) * (1.0f / 128.0f);
    float d = (t < 128) ? (h - mu) : 0.0f;
    float var = bsum(d * d, red) * (1.0f / 128.0f);
    if (t < 128) zln[t] = lnzw[t] * d * rsqrtf(var + 1e-12f) + lnzb[t];

    for (int k = 0; k < 8; k++) {
        float p = (t < 128) ? protos[k * 128 + t] : 0.0f;
        float pu = bsum(p, red) * (1.0f / 128.0f);
        float pd = (t < 128) ? (p - pu) : 0.0f;
        float pv = bsum(pd * pd, red) * (1.0f / 128.0f);
        if (t < 128) pl[k][t] = lnpw[t] * pd * rsqrtf(pv + 1e-12f) + lnpb[t];
    }
    __syncthreads();

    for (int k = 0; k < 8; k++) {
        float pp = (t < 128) ? zln[t] * pl[k][t] : 0.0f;
        float s = bsum(pp, red);
        if (t == 0) dotk[k] = s * 0.08838834764831845f;
    }
    __syncthreads();
    if (t < 8) {
        float m = -1e30f;
        for (int kk = 0; kk < 8; kk++) m = fmaxf(m, dotk[kk]);
        float s = 0.f;
        for (int kk = 0; kk < 8; kk++) s += expf(dotk[kk] - m);
        attnv[t] = expf(dotk[t] - m) / s;
    }
    __syncthreads();

    float zacc = 0.0f;
    for (int k = 0; k < 8; k++) {
        float v = (t < 128) ? (beta[k * 128 + t] + attnv[k] * h) : 0.0f;
        float vu = bsum(v, red) * (1.0f / 128.0f);
        float vd = (t < 128) ? (v - vu) : 0.0f;
        float vv = bsum(vd * vd, red) * (1.0f / 128.0f);
        if (t < 128) {
            float dval = lnaw[t] * vd * rsqrtf(vv + 1e-12f) + lnab[t];
            out[OFF_DIS + ((size_t)b * 8 + k) * 128 + t] = dval;
            zacc += dval;
        }
    }
    if (t < 128) {
        float zv = zacc * 0.125f;
        zfull[t] = zv;
        out[OFF_Z + (size_t)b * 129 + t] = zv;
    }
    if (t == 0) {
        zfull[128] = rc;
        out[OFF_Z + (size_t)b * 129 + 128] = rc;
    }
    __syncthreads();

    if (t < 10) {
        float acc = e1b[t];
        for (int i = 0; i < 129; i++) acc = fmaf(e1W[t * 129 + i], zfull[i], acc);
        h1s[t] = tanhf(acc);
    }
    __syncthreads();
    if (t < 4) {
        float acc = e2b[t];
        for (int i = 0; i < 10; i++) acc = fmaf(e2W[t * 10 + i], h1s[i], acc);
        lg[t] = acc;
    }
    __syncthreads();
    if (t < 4) {
        float m = fmaxf(fmaxf(lg[0], lg[1]), fmaxf(lg[2], lg[3]));
        float s = expf(lg[0] - m) + expf(lg[1] - m) + expf(lg[2] - m) + expf(lg[3] - m);
        out[OFF_GAMMA + (size_t)b * 4 + t] = expf(lg[t] - m) / s;
    }
}

__global__ void epiB(float* __restrict__ out, const int* __restrict__ perm) {
    int b = blockIdx.x;
    for (int e = threadIdx.x; e < 1024; e += blockDim.x) {
        int k = e >> 7, j = e & 127;
        int src = perm[k * 256 + b];
        out[OFF_DISP + ((size_t)b * 8 + k) * 128 + j] =
            out[OFF_DIS + ((size_t)src * 8 + k) * 128 + j];
    }
}

// ---------------------------------------------------------------------------
extern "C" void kernel_launch(void* const* d_in, const int* in_sizes, int n_in,
                              void* d_out, int out_size) {
    const float* input   = (const float*)d_in[0];
    const float* enc_Wih = (const float*)d_in[1];
    const float* enc_Whh = (const float*)d_in[2];
    const float* enc_bih = (const float*)d_in[3];
    const float* enc_bhh = (const float*)d_in[4];
    const float* dec_Wih = (const float*)d_in[5];
    const float* dec_Whh = (const float*)d_in[6];
    const float* dec_bih = (const float*)d_in[7];
    const float* dec_bhh = (const float*)d_in[8];
    const float* out_W   = (const float*)d_in[9];
    const float* out_b   = (const float*)d_in[10];
    const float* protos  = (const float*)d_in[11];
    const float* lnz_w   = (const float*)d_in[12];
    const float* lnz_b   = (const float*)d_in[13];
    const float* lnp_w   = (const float*)d_in[14];
    const float* lnp_b   = (const float*)d_in[15];
    const float* lna_w   = (const float*)d_in[16];
    const float* lna_b   = (const float*)d_in[17];
    const float* beta    = (const float*)d_in[18];
    const float* est1_W  = (const float*)d_in[19];
    const float* est1_b  = (const float*)d_in[20];
    const float* est2_W  = (const float*)d_in[21];
    const float* est2_b  = (const float*)d_in[22];
    float* out = (float*)d_out;

    int* perm_ptr = nullptr;
    cudaGetSymbolAddress((void**)&perm_ptr, g_perm);

    cudaFuncSetAttribute(dec_kernel, cudaFuncAttributeMaxDynamicSharedMemorySize, 204288);
    cudaFuncSetAttribute(mma_gemm_gi, cudaFuncAttributeMaxDynamicSharedMemorySize, MMA_SMEM);
    cudaFuncSetAttribute(mma_gemm_out, cudaFuncAttributeMaxDynamicSharedMemorySize, MMA_SMEM);

    // 1. bf16 split conversion of weights
    conv_w<<<24, 256>>>(enc_Wih);
    conv_ow<<<8, 256>>>(out_W);
    // 2. Tensor-core gi GEMM (split-bf16, 3 terms; X split in-kernel)
    mma_gemm_gi<<<dim3(3, 1024), 256, MMA_SMEM>>>(input, enc_bih);
    // 3. Encoder recurrence (fast gates)
    enc_kernel<<<128, 384>>>(enc_Whh, enc_bhh);
    // 4. Fold output projection into decoder input weights
    fold_kernel<<<384, 128>>>(dec_Wih, out_W, out_b, dec_bih);
    // 5. Decoder recurrence (fast gates, writes bf16 h split directly)
    dec_kernel<<<128, 384, 204288>>>(dec_Whh, dec_bhh);
    // 6. Tensor-core out GEMM (A = h split written by dec)
    mma_gemm_out<<<1024, 256, MMA_SMEM>>>(out_b, out);
    // 7. JAX-exact permutations
    perm_kernel<<<1, 256>>>(perm_ptr);
    // 8. Epilogue (shuffle reductions)
    epiA<<<256, 256>>>(input, protos, lnz_w, lnz_b, lnp_w, lnp_b, lna_w, lna_b,
                       beta, est1_W, est1_b, est2_W, est2_b, out);
    // 9. dis_perm gather
    epiB<<<256, 256>>>(out, perm_ptr);
}

// round 16
// speedup vs baseline: 1.1238x; 1.0135x over previous
#include <cuda_runtime.h>
#include <cuda_bf16.h>
#include <math.h>
#include <stdint.h>
#include <stddef.h>

// Problem dims
#define Bsz 256
#define Ssz 512
#define Fdim 128
#define Hdim 128
#define G3  384   // 3*H

// Output layout (tuple flattened): h_enc, output, z, gamma, dis, dis_perm
#define OFF_HENC  ((size_t)0)
#define OFF_OUT   ((size_t)32768)                       // 256*128
#define OFF_Z     ((size_t)(32768 + 16777216))          // + 256*512*128
#define OFF_GAMMA ((size_t)(OFF_Z + 256*129))
#define OFF_DIS   ((size_t)(OFF_GAMMA + 256*4))
#define OFF_DISP  ((size_t)(OFF_DIS + 256*8*128))

typedef unsigned long long ull;

// Scratch (device globals; no allocations allowed)
__device__ float g_Genc[(size_t)Ssz * Bsz * G3];    // [t][b][g]  192 MB
__device__ float g_Henc[Bsz * Hdim];
__device__ float g_Mf[G3 * Hdim];
__device__ float g_bf[G3];
__device__ int   g_perm[8 * Bsz];
// bf16 split h-trajectory written by the decoder for the out GEMM.
__device__ __nv_bfloat16 g_Xh[(size_t)131072 * 128];   // 33.5 MB
__device__ __nv_bfloat16 g_Xl[(size_t)131072 * 128];
__device__ __nv_bfloat16 g_Wh[G3 * 128];
__device__ __nv_bfloat16 g_Wl[G3 * 128];
__device__ __nv_bfloat16 g_Oh[128 * 128];              // out_W split
__device__ __nv_bfloat16 g_Ol[128 * 128];

// Fast gate math
__device__ __forceinline__ float sigf(float x) { return 1.0f / (1.0f + __expf(-x)); }
__device__ __forceinline__ float tanh_fast(float x) {
    float t = __expf(-2.0f * fabsf(x));
    float r = (1.0f - t) / (1.0f + t);
    return copysignf(r, x);
}

// ---- packed f32x2 helpers (dec only) ----
__device__ __forceinline__ ull pk2(float lo, float hi) {
    ull r; asm("mov.b64 %0, {%1, %2};" : "=l"(r) : "f"(lo), "f"(hi)); return r;
}
__device__ __forceinline__ ull f2fma(ull a, ull b, ull c) {
    ull d; asm("fma.rn.f32x2 %0, %1, %2, %3;" : "=l"(d) : "l"(a), "l"(b), "l"(c)); return d;
}
__device__ __forceinline__ float psum(ull v) {
    float a, b; asm("mov.b64 {%0, %1}, %2;" : "=f"(a), "=f"(b) : "l"(v)); return a + b;
}

__device__ __forceinline__ unsigned smaddr(const void* p) {
    unsigned a;
    asm("{ .reg .u64 t; cvta.to.shared.u64 t, %1; cvt.u32.u64 %0, t; }" : "=r"(a) : "l"(p));
    return a;
}

__device__ __forceinline__ void ldsm4(unsigned* f, unsigned addr) {
    asm volatile("ldmatrix.sync.aligned.m8n8.x4.shared.b16 {%0,%1,%2,%3}, [%4];"
                 : "=r"(f[0]), "=r"(f[1]), "=r"(f[2]), "=r"(f[3]) : "r"(addr));
}
__device__ __forceinline__ void mma16816(float* d, const unsigned* a, unsigned b0, unsigned b1) {
    asm volatile(
        "mma.sync.aligned.m16n8k16.row.col.f32.bf16.bf16.f32 "
        "{%0,%1,%2,%3}, {%4,%5,%6,%7}, {%8,%9}, {%0,%1,%2,%3};"
        : "+f"(d[0]), "+f"(d[1]), "+f"(d[2]), "+f"(d[3])
        : "r"(a[0]), "r"(a[1]), "r"(a[2]), "r"(a[3]), "r"(b0), "r"(b1));
}

// ---------------------------------------------------------------------------
// Threefry2x32 (exact JAX constants)
// ---------------------------------------------------------------------------
__device__ __forceinline__ uint2 threefry(unsigned k0, unsigned k1,
                                          unsigned x0, unsigned x1) {
    unsigned ks2 = k0 ^ k1 ^ 0x1BD11BDAu;
    x0 += k0; x1 += k1;
#define TFR(r) { x0 += x1; x1 = (x1 << (r)) | (x1 >> (32 - (r))); x1 ^= x0; }
    TFR(13) TFR(15) TFR(26) TFR(6)   x0 += k1;  x1 += ks2 + 1u;
    TFR(17) TFR(29) TFR(16) TFR(24)  x0 += ks2; x1 += k0 + 2u;
    TFR(13) TFR(15) TFR(26) TFR(6)   x0 += k0;  x1 += k1 + 3u;
    TFR(17) TFR(29) TFR(16) TFR(24)  x0 += k1;  x1 += ks2 + 4u;
    TFR(13) TFR(15) TFR(26) TFR(6)   x0 += ks2; x1 += k0 + 5u;
#undef TFR
    return make_uint2(x0, x1);
}

// ---------------------------------------------------------------------------
// prep_kernel: conv_w (blocks 0-23) + conv_ow (24-31) + fold (32-415) + perm (416)
// Each block takes exactly one uniform branch.
// ---------------------------------------------------------------------------
__global__ void prep_kernel(const float* __restrict__ encWih,
                            const float* __restrict__ outW,
                            const float* __restrict__ dWih,
                            const float* __restrict__ outb,
                            const float* __restrict__ dbih,
                            int* __restrict__ perm) {
    int blk = blockIdx.x;
    int tid = threadIdx.x;
    if (blk < 24) {
        // enc_Wih split: 6144 chunks of 8
        unsigned c = blk * 256 + tid;
        int k0 = (c & 15) * 8;
        int gt = (int)(c >> 4);
        const float* src = encWih + ((size_t)gt * 128 + k0);
        size_t dst = (size_t)gt * 128 + k0;
#pragma unroll
        for (int i = 0; i < 8; i++) {
            float x = src[i];
            __nv_bfloat16 h = __float2bfloat16(x);
            g_Wh[dst + i] = h;
            g_Wl[dst + i] = __float2bfloat16(x - __bfloat162float(h));
        }
    } else if (blk < 32) {
        // out_W split: 2048 chunks of 8
        unsigned c = (blk - 24) * 256 + tid;
        size_t base = (size_t)c * 8;
#pragma unroll
        for (int i = 0; i < 8; i++) {
            float x = outW[base + i];
            __nv_bfloat16 h = __float2bfloat16(x);
            g_Oh[base + i] = h;
            g_Ol[base + i] = __float2bfloat16(x - __bfloat162float(h));
        }
    } else if (blk < 416) {
        // fold: Mf[g][:] and bf[g], g = blk-32
        __shared__ float wrow[128];
        __shared__ float red[128];
        int g = blk - 32, j = tid;
        if (j < 128) wrow[j] = dWih[g * 128 + j];
        __syncthreads();
        if (j < 128) {
            float acc = 0.0f;
#pragma unroll 8
            for (int f = 0; f < 128; f++) acc = fmaf(wrow[f], outW[f * 128 + j], acc);
            g_Mf[g * 128 + j] = acc;
            red[j] = wrow[j] * outb[j];
        }
        __syncthreads();
        for (int s = 64; s > 0; s >>= 1) {
            if (j < s) red[j] += red[j + s];
            __syncthreads();
        }
        if (j == 0) g_bf[g] = dbih[g] + red[0];
    } else {
        // perm (JAX threefry_partitionable reproduction)
        __shared__ unsigned sk[8][2];
        __shared__ unsigned bits[256];
        int t = tid;
        if (t < 8) {
            uint2 pk = threefry(0u, 42u, 0u, (unsigned)t);
            uint2 s  = threefry(pk.x, pk.y, 0u, 1u);
            sk[t][0] = s.x; sk[t][1] = s.y;
        }
        __syncthreads();
        for (int k = 0; k < 8; k++) {
            uint2 y = threefry(sk[k][0], sk[k][1], 0u, (unsigned)t);
            bits[t] = y.x ^ y.y;
            __syncthreads();
            unsigned mine = bits[t];
            int rank = 0;
            for (int j = 0; j < 256; j++) {
                unsigned o = bits[j];
                rank += (o < mine) || (o == mine && j < t);
            }
            perm[k * 256 + rank] = t;
            __syncthreads();
        }
    }
}

// ---------------------------------------------------------------------------
// HMMA gi GEMM (split-bf16, 3 terms), M-tile 64 for 2 CTAs/SM:
// g_Genc[r][g] = x[r,:].W[g,:] + bias.  Grid (3, 2048).
// smem: (2*64 + 2*128) * APAD bf16 = 104448 B.
// ---------------------------------------------------------------------------
#define APAD 136
#define MMA_SMEM (384 * APAD * 2)   // 104448 B

__global__ void __launch_bounds__(256) mma_gemm_gi(const float* __restrict__ X,
                                                   const float* __restrict__ bias) {
    extern __shared__ __align__(16) __nv_bfloat16 sm[];
    __nv_bfloat16* sAh = sm;                    // 64*APAD
    __nv_bfloat16* sAl = sm + 64 * APAD;
    __nv_bfloat16* sBh = sm + 128 * APAD;       // 128*APAD
    __nv_bfloat16* sBl = sm + 256 * APAD;
    __shared__ float bias_s[128];
    int tid = threadIdx.x;
    int wid = tid >> 5, lane = tid & 31;
    int n0 = blockIdx.x * 128;
    size_t rBase = (size_t)blockIdx.y * 64;

    if (tid < 128) bias_s[tid] = bias[n0 + tid];

    // Load A (64 rows) from fp32 X with on-the-fly hi/lo bf16 split.
#pragma unroll
    for (int i = 0; i < 4; i++) {
        int c = tid + i * 256;
        int r = c >> 4, k0 = (c & 15) * 8;
        size_t R = rBase + r;
        int bb = (int)(R & 255), tt = (int)(R >> 8);
        const float* xp = X + (((size_t)bb * 512 + tt) * 128 + k0);
        float4 xa = *(const float4*)xp;
        float4 xb = *(const float4*)(xp + 4);
        float xs[8] = {xa.x, xa.y, xa.z, xa.w, xb.x, xb.y, xb.z, xb.w};
        __nv_bfloat16 hb[8], lb[8];
#pragma unroll
        for (int e = 0; e < 8; e++) {
            __nv_bfloat16 h = __float2bfloat16(xs[e]);
            hb[e] = h;
            lb[e] = __float2bfloat16(xs[e] - __bfloat162float(h));
        }
        *(uint4*)&sAh[r * APAD + k0] = *(uint4*)hb;
        *(uint4*)&sAl[r * APAD + k0] = *(uint4*)lb;
    }
    // Load B (128 rows)
#pragma unroll
    for (int i = 0; i < 8; i++) {
        int c = tid + i * 256;
        int r = c >> 4, k0 = (c & 15) * 8;
        uint4 vh = *(const uint4*)&g_Wh[(size_t)(n0 + r) * 128 + k0];
        uint4 vl = *(const uint4*)&g_Wl[(size_t)(n0 + r) * 128 + k0];
        *(uint4*)&sBh[r * APAD + k0] = vh;
        *(uint4*)&sBl[r * APAD + k0] = vl;
    }
    __syncthreads();

    int wm = wid >> 1, wn = wid & 1;   // 4 M x 2 N warps; warp tile 16x64
    float d[8][4];
#pragma unroll
    for (int nf = 0; nf < 8; nf++)
#pragma unroll
        for (int e = 0; e < 4; e++) d[nf][e] = 0.0f;

    int aRow = wm * 16 + (lane & 7) + ((lane >> 3) & 1) * 8;
    int aCol = (lane >> 4) * 8;
    int bRow = wn * 64 + (lane & 7) + ((lane >= 16) ? 8 : 0);
    int bCol = ((lane >> 3) & 1) * 8;

    for (int ks = 0; ks < 8; ks++) {
        int k0 = ks * 16;
        unsigned ah[4], al[4];
        {
            unsigned off = (unsigned)(aRow * APAD + k0 + aCol) * 2u;
            ldsm4(ah, smaddr(sAh) + off);
            ldsm4(al, smaddr(sAl) + off);
        }
#pragma unroll
        for (int np = 0; np < 4; np++) {
            unsigned off = (unsigned)((bRow + np * 16) * APAD + k0 + bCol) * 2u;
            unsigned bh[4], bl[4];
            ldsm4(bh, smaddr(sBh) + off);
            ldsm4(bl, smaddr(sBl) + off);
            mma16816(d[np * 2],     ah, bh[0], bh[1]);
            mma16816(d[np * 2 + 1], ah, bh[2], bh[3]);
            mma16816(d[np * 2],     ah, bl[0], bl[1]);
            mma16816(d[np * 2 + 1], ah, bl[2], bl[3]);
            mma16816(d[np * 2],     al, bh[0], bh[1]);
            mma16816(d[np * 2 + 1], al, bh[2], bh[3]);
        }
    }

    int group = lane >> 2, tg = lane & 3;
#pragma unroll
    for (int nf = 0; nf < 8; nf++) {
        int row = wm * 16 + group;
        int col = wn * 64 + nf * 8 + tg * 2;
        size_t r = rBase + row;
        float b0 = bias_s[col], b1 = bias_s[col + 1];
        float2 v0 = make_float2(d[nf][0] + b0, d[nf][1] + b1);
        float2 v1 = make_float2(d[nf][2] + b0, d[nf][3] + b1);
        *(float2*)&g_Genc[r * 384 + n0 + col] = v0;
        *(float2*)&g_Genc[(r + 8) * 384 + n0 + col] = v1;
    }
}

// ---------------------------------------------------------------------------
// HMMA out GEMM (split-bf16), M-tile 64. A = g_Xh/g_Xl (h split). Grid 2048.
// ---------------------------------------------------------------------------
__global__ void __launch_bounds__(256) mma_gemm_out(const float* __restrict__ bias,
                                                    float* __restrict__ out) {
    extern __shared__ __align__(16) __nv_bfloat16 sm[];
    __nv_bfloat16* sAh = sm;
    __nv_bfloat16* sAl = sm + 64 * APAD;
    __nv_bfloat16* sBh = sm + 128 * APAD;
    __nv_bfloat16* sBl = sm + 256 * APAD;
    __shared__ float bias_s[128];
    int tid = threadIdx.x;
    int wid = tid >> 5, lane = tid & 31;
    size_t rBase = (size_t)blockIdx.x * 64;

    if (tid < 128) bias_s[tid] = bias[tid];

#pragma unroll
    for (int i = 0; i < 4; i++) {
        int c = tid + i * 256;
        int r = c >> 4, k0 = (c & 15) * 8;
        uint4 vh = *(const uint4*)&g_Xh[(rBase + r) * 128 + k0];
        uint4 vl = *(const uint4*)&g_Xl[(rBase + r) * 128 + k0];
        *(uint4*)&sAh[r * APAD + k0] = vh;
        *(uint4*)&sAl[r * APAD + k0] = vl;
    }
#pragma unroll
    for (int i = 0; i < 8; i++) {
        int c = tid + i * 256;
        int r = c >> 4, k0 = (c & 15) * 8;
        uint4 vh = *(const uint4*)&g_Oh[(size_t)r * 128 + k0];
        uint4 vl = *(const uint4*)&g_Ol[(size_t)r * 128 + k0];
        *(uint4*)&sBh[r * APAD + k0] = vh;
        *(uint4*)&sBl[r * APAD + k0] = vl;
    }
    __syncthreads();

    int wm = wid >> 1, wn = wid & 1;
    float d[8][4];
#pragma unroll
    for (int nf = 0; nf < 8; nf++)
#pragma unroll
        for (int e = 0; e < 4; e++) d[nf][e] = 0.0f;

    int aRow = wm * 16 + (lane & 7) + ((lane >> 3) & 1) * 8;
    int aCol = (lane >> 4) * 8;
    int bRow = wn * 64 + (lane & 7) + ((lane >= 16) ? 8 : 0);
    int bCol = ((lane >> 3) & 1) * 8;

    for (int ks = 0; ks < 8; ks++) {
        int k0 = ks * 16;
        unsigned ah[4], al[4];
        {
            unsigned off = (unsigned)(aRow * APAD + k0 + aCol) * 2u;
            ldsm4(ah, smaddr(sAh) + off);
            ldsm4(al, smaddr(sAl) + off);
        }
#pragma unroll
        for (int np = 0; np < 4; np++) {
            unsigned off = (unsigned)((bRow + np * 16) * APAD + k0 + bCol) * 2u;
            unsigned bh[4], bl[4];
            ldsm4(bh, smaddr(sBh) + off);
            ldsm4(bl, smaddr(sBl) + off);
            mma16816(d[np * 2],     ah, bh[0], bh[1]);
            mma16816(d[np * 2 + 1], ah, bh[2], bh[3]);
            mma16816(d[np * 2],     ah, bl[0], bl[1]);
            mma16816(d[np * 2 + 1], ah, bl[2], bl[3]);
            mma16816(d[np * 2],     al, bh[0], bh[1]);
            mma16816(d[np * 2 + 1], al, bh[2], bh[3]);
        }
    }

    // Epilogue with time reversal: r = i*256+b -> output[b][511-i][:]
    int group = lane >> 2, tg = lane & 3;
#pragma unroll
    for (int nf = 0; nf < 8; nf++) {
        int row = wm * 16 + group;
        int col = wn * 64 + nf * 8 + tg * 2;
        float b0 = bias_s[col], b1 = bias_s[col + 1];
        size_t r0 = rBase + row;
        size_t r1 = r0 + 8;
        int is0 = (int)(r0 >> 8), bb0 = (int)(r0 & 255);
        int is1 = (int)(r1 >> 8), bb1 = (int)(r1 & 255);
        size_t o0 = (size_t)(bb0 * 512 + (511 - is0)) * 128;
        size_t o1 = (size_t)(bb1 * 512 + (511 - is1)) * 128;
        float2 v0 = make_float2(d[nf][0] + b0, d[nf][1] + b1);
        float2 v1 = make_float2(d[nf][2] + b0, d[nf][3] + b1);
        *(float2*)&out[OFF_OUT + o0 + col] = v0;
        *(float2*)&out[OFF_OUT + o1 + col] = v1;
    }
}

// ---------------------------------------------------------------------------
// Encoder recurrence (scalar FMA, fast gates)
// ---------------------------------------------------------------------------
__global__ void __launch_bounds__(384, 1) enc_kernel(const float* __restrict__ Whh,
                                                     const float* __restrict__ bhh) {
    __shared__ float h_sm[2][128];
    __shared__ float gh_sm[2][384];
    int g = threadIdx.x;
    int b0 = blockIdx.x * 2;
    float w[128];
#pragma unroll
    for (int k = 0; k < 128; k += 4) {
        float4 v = *(const float4*)&Whh[(size_t)g * 128 + k];
        w[k] = v.x; w[k + 1] = v.y; w[k + 2] = v.z; w[k + 3] = v.w;
    }
    float bg = bhh[g];
    int bb = g >> 7, j = g & 127;
    if (g < 256) h_sm[bb][j] = 0.0f;
    __syncthreads();

    for (int t = 0; t < 512; t++) {
        float gi_r = 0.f, gi_z = 0.f, gi_n = 0.f;
        if (g < 256) {
            const float* gp = g_Genc + ((size_t)t * 256 + b0 + bb) * 384;
            gi_r = gp[j]; gi_z = gp[128 + j]; gi_n = gp[256 + j];
        }
        float a0 = bg, a1 = bg;
#pragma unroll
        for (int k = 0; k < 128; k += 4) {
            float4 h0 = *(const float4*)&h_sm[0][k];
            float4 h1 = *(const float4*)&h_sm[1][k];
            a0 = fmaf(w[k], h0.x, a0);     a1 = fmaf(w[k], h1.x, a1);
            a0 = fmaf(w[k + 1], h0.y, a0); a1 = fmaf(w[k + 1], h1.y, a1);
            a0 = fmaf(w[k + 2], h0.z, a0); a1 = fmaf(w[k + 2], h1.z, a1);
            a0 = fmaf(w[k + 3], h0.w, a0); a1 = fmaf(w[k + 3], h1.w, a1);
        }
        gh_sm[0][g] = a0;
        gh_sm[1][g] = a1;
        __syncthreads();
        if (g < 256) {
            float r = sigf(gi_r + gh_sm[bb][j]);
            float z = sigf(gi_z + gh_sm[bb][128 + j]);
            float n = tanh_fast(gi_n + r * gh_sm[bb][256 + j]);
            h_sm[bb][j] = (1.0f - z) * n + z * h_sm[bb][j];
        }
        __syncthreads();
    }
    if (g < 256) g_Henc[(b0 + bb) * 128 + j] = h_sm[bb][j];
}

// ---------------------------------------------------------------------------
// Decoder recurrence (R7 core; fast gates; writes h split to g_Xh/g_Xl)
// ---------------------------------------------------------------------------
__global__ void __launch_bounds__(384, 1) dec_kernel(const float* __restrict__ Whh,
                                                     const float* __restrict__ bhh) {
    extern __shared__ __align__(16) unsigned char dsm[];
    ulonglong2* wq = (ulonglong2*)dsm;                 // [32][384] -> 196608 B
    float* hsm = (float*)(dsm + 196608);
    float* gis = hsm + 256;
    float* ghs = gis + 768;
    int g = threadIdx.x;
    int b0 = blockIdx.x * 2;
    int bb = g >> 7, j = g & 127;

    ull w2[64];
    {
        const ull* wrow = (const ull*)g_Mf + (size_t)g * 64;
#pragma unroll
        for (int kp = 0; kp < 64; kp++) w2[kp] = wrow[kp];
    }
    float bfg = g_bf[g];
    float bhg = bhh[g];

    for (int idx = g; idx < 384 * 32; idx += 384) {
        int gg = idx >> 5, q = idx & 31;
        wq[q * 384 + gg] = ((const ulonglong2*)Whh)[(size_t)gg * 32 + q];
    }
    if (g < 256) {
        float h_init = g_Henc[b0 * 128 + g];
        hsm[g] = h_init;
        __nv_bfloat16 hh = __float2bfloat16(h_init);
        size_t row = ((size_t)0 * 256 + b0 + bb) * 128 + j;
        g_Xh[row] = hh;
        g_Xl[row] = __float2bfloat16(h_init - __bfloat162float(hh));
    }
    __syncthreads();

    for (int i = 0; i < 512; i++) {
        ull gi0 = pk2(bfg, 0.f), gi1 = pk2(bfg, 0.f);
        ull gh0 = pk2(bhg, 0.f), gh1 = pk2(bhg, 0.f);
#pragma unroll
        for (int grp = 0; grp < 16; grp++) {
            ulonglong2 wvA = wq[(2 * grp) * 384 + g];
            ulonglong2 wvB = wq[(2 * grp + 1) * 384 + g];
            ulonglong2 h0A = *(const ulonglong2*)&hsm[8 * grp];
            ulonglong2 h0B = *(const ulonglong2*)&hsm[8 * grp + 4];
            ulonglong2 h1A = *(const ulonglong2*)&hsm[128 + 8 * grp];
            ulonglong2 h1B = *(const ulonglong2*)&hsm[128 + 8 * grp + 4];
            gi0 = f2fma(w2[4 * grp],     h0A.x, gi0);
            gi1 = f2fma(w2[4 * grp],     h1A.x, gi1);
            gi0 = f2fma(w2[4 * grp + 1], h0A.y, gi0);
            gi1 = f2fma(w2[4 * grp + 1], h1A.y, gi1);
            gi0 = f2fma(w2[4 * grp + 2], h0B.x, gi0);
            gi1 = f2fma(w2[4 * grp + 2], h1B.x, gi1);
            gi0 = f2fma(w2[4 * grp + 3], h0B.y, gi0);
            gi1 = f2fma(w2[4 * grp + 3], h1B.y, gi1);
            gh0 = f2fma(wvA.x, h0A.x, gh0);
            gh1 = f2fma(wvA.x, h1A.x, gh1);
            gh0 = f2fma(wvA.y, h0A.y, gh0);
            gh1 = f2fma(wvA.y, h1A.y, gh1);
            gh0 = f2fma(wvB.x, h0B.x, gh0);
            gh1 = f2fma(wvB.x, h1B.x, gh1);
            gh0 = f2fma(wvB.y, h0B.y, gh0);
            gh1 = f2fma(wvB.y, h1B.y, gh1);
        }
        gis[g] = psum(gi0); gis[384 + g] = psum(gi1);
        ghs[g] = psum(gh0); ghs[384 + g] = psum(gh1);
        __syncthreads();
        if (g < 256) {
            int base = bb * 384;
            float r = sigf(gis[base + j] + ghs[base + j]);
            float z = sigf(gis[base + 128 + j] + ghs[base + 128 + j]);
            float n = tanh_fast(gis[base + 256 + j] + r * ghs[base + 256 + j]);
            float h_new = (1.0f - z) * n + z * hsm[g];
            hsm[g] = h_new;
            if (i < 511) {
                __nv_bfloat16 hh = __float2bfloat16(h_new);
                size_t row = ((size_t)(i + 1) * 256 + b0 + bb) * 128 + j;
                g_Xh[row] = hh;
                g_Xl[row] = __float2bfloat16(h_new - __bfloat162float(hh));
            }
        }
        __syncthreads();
    }
}

// ---------------------------------------------------------------------------
// Epilogues (shuffle-based reductions)
// ---------------------------------------------------------------------------
__device__ __forceinline__ float bsum(float v, float* red) {
    __syncthreads();
#pragma unroll
    for (int o = 16; o > 0; o >>= 1)
        v += __shfl_xor_sync(0xffffffffu, v, o);
    if ((threadIdx.x & 31) == 0) red[threadIdx.x >> 5] = v;
    __syncthreads();
    float s = red[0];
#pragma unroll
    for (int w = 1; w < 8; w++) s += red[w];
    return s;
}

__global__ void __launch_bounds__(256) epiA(
    const float* __restrict__ X,
    const float* __restrict__ protos,
    const float* __restrict__ lnzw, const float* __restrict__ lnzb,
    const float* __restrict__ lnpw, const float* __restrict__ lnpb,
    const float* __restrict__ lnaw, const float* __restrict__ lnab,
    const float* __restrict__ beta,
    const float* __restrict__ e1W, const float* __restrict__ e1b,
    const float* __restrict__ e2W, const float* __restrict__ e2b,
    float* __restrict__ out) {
    int b = blockIdx.x, t = threadIdx.x;
    __shared__ float red[8];
    __shared__ float zln[128];
    __shared__ float pl[8][128];
    __shared__ float dotk[8];
    __shared__ float attnv[8];
    __shared__ float zfull[129];
    __shared__ float h1s[10];
    __shared__ float lg[4];

    const float* a = X + (size_t)b * 65536;
    const float* o = out + OFF_OUT + (size_t)b * 65536;
    float sab = 0.f, saa = 0.f, sbb = 0.f;
    for (int i = t; i < 65536; i += 256) {
        float av = a[i], bv = o[i];
        sab = fmaf(av, bv, sab);
        saa = fmaf(av, av, saa);
        sbb = fmaf(bv, bv, sbb);
    }
    sab = bsum(sab, red);
    saa = bsum(saa, red);
    sbb = bsum(sbb, red);
    float rc = sab / (fmaxf(sqrtf(saa), 1e-8f) * fmaxf(sqrtf(sbb), 1e-8f));

    float h = (t < 128) ? g_Henc[b * 128 + t] : 0.0f;
    if (t < 128) out[OFF_HENC + b * 128 + t] = h;
    float mu = bsum(h, red) * (1.0f / 128.0f);
    float d = (t < 128) ? (h - mu) : 0.0f;
    float var = bsum(d * d, red) * (1.0f / 128.0f);
    if (t < 128) zln[t] = lnzw[t] * d * rsqrtf(var + 1e-12f) + lnzb[t];

    for (int k = 0; k < 8; k++) {
        float p = (t < 128) ? protos[k * 128 + t] : 0.0f;
        float pu = bsum(p, red) * (1.0f / 128.0f);
        float pd = (t < 128) ? (p - pu) : 0.0f;
        float pv = bsum(pd * pd, red) * (1.0f / 128.0f);
        if (t < 128) pl[k][t] = lnpw[t] * pd * rsqrtf(pv + 1e-12f) + lnpb[t];
    }
    __syncthreads();

    for (int k = 0; k < 8; k++) {
        float pp = (t < 128) ? zln[t] * pl[k][t] : 0.0f;
        float s = bsum(pp, red);
        if (t == 0) dotk[k] = s * 0.08838834764831845f;
    }
    __syncthreads();
    if (t < 8) {
        float m = -1e30f;
        for (int kk = 0; kk < 8; kk++) m = fmaxf(m, dotk[kk]);
        float s = 0.f;
        for (int kk = 0; kk < 8; kk++) s += expf(dotk[kk] - m);
        attnv[t] = expf(dotk[t] - m) / s;
    }
    __syncthreads();

    float zacc = 0.0f;
    for (int k = 0; k < 8; k++) {
        float v = (t < 128) ? (beta[k * 128 + t] + attnv[k] * h) : 0.0f;
        float vu = bsum(v, red) * (1.0f / 128.0f);
        float vd = (t < 128) ? (v - vu) : 0.0f;
        float vv = bsum(vd * vd, red) * (1.0f / 128.0f);
        if (t < 128) {
            float dval = lnaw[t] * vd * rsqrtf(vv + 1e-12f) + lnab[t];
            out[OFF_DIS + ((size_t)b * 8 + k) * 128 + t] = dval;
            zacc += dval;
        }
    }
    if (t < 128) {
        float zv = zacc * 0.125f;
        zfull[t] = zv;
        out[OFF_Z + (size_t)b * 129 + t] = zv;
    }
    if (t == 0) {
        zfull[128] = rc;
        out[OFF_Z + (size_t)b * 129 + 128] = rc;
    }
    __syncthreads();

    if (t < 10) {
        float acc = e1b[t];
        for (int i = 0; i < 129; i++) acc = fmaf(e1W[t * 129 + i], zfull[i], acc);
        h1s[t] = tanhf(acc);
    }
    __syncthreads();
    if (t < 4) {
        float acc = e2b[t];
        for (int i = 0; i < 10; i++) acc = fmaf(e2W[t * 10 + i], h1s[i], acc);
        lg[t] = acc;
    }
    __syncthreads();
    if (t < 4) {
        float m = fmaxf(fmaxf(lg[0], lg[1]), fmaxf(lg[2], lg[3]));
        float s = expf(lg[0] - m) + expf(lg[1] - m) + expf(lg[2] - m) + expf(lg[3] - m);
        out[OFF_GAMMA + (size_t)b * 4 + t] = expf(lg[t] - m) / s;
    }
}

__global__ void epiB(float* __restrict__ out, const int* __restrict__ perm) {
    int b = blockIdx.x;
    for (int e = threadIdx.x; e < 1024; e += blockDim.x) {
        int k = e >> 7, j = e & 127;
        int src = perm[k * 256 + b];
        out[OFF_DISP + ((size_t)b * 8 + k) * 128 + j] =
            out[OFF_DIS + ((size_t)src * 8 + k) * 128 + j];
    }
}

// ---------------------------------------------------------------------------
extern "C" void kernel_launch(void* const* d_in, const int* in_sizes, int n_in,
                              void* d_out, int out_size) {
    const float* input   = (const float*)d_in[0];
    const float* enc_Wih = (const float*)d_in[1];
    const float* enc_Whh = (const float*)d_in[2];
    const float* enc_bih = (const float*)d_in[3];
    const float* enc_bhh = (const float*)d_in[4];
    const float* dec_Wih = (const float*)d_in[5];
    const float* dec_Whh = (const float*)d_in[6];
    const float* dec_bih = (const float*)d_in[7];
    const float* dec_bhh = (const float*)d_in[8];
    const float* out_W   = (const float*)d_in[9];
    const float* out_b   = (const float*)d_in[10];
    const float* protos  = (const float*)d_in[11];
    const float* lnz_w   = (const float*)d_in[12];
    const float* lnz_b   = (const float*)d_in[13];
    const float* lnp_w   = (const float*)d_in[14];
    const float* lnp_b   = (const float*)d_in[15];
    const float* lna_w   = (const float*)d_in[16];
    const float* lna_b   = (const float*)d_in[17];
    const float* beta    = (const float*)d_in[18];
    const float* est1_W  = (const float*)d_in[19];
    const float* est1_b  = (const float*)d_in[20];
    const float* est2_W  = (const float*)d_in[21];
    const float* est2_b  = (const float*)d_in[22];
    float* out = (float*)d_out;

    int* perm_ptr = nullptr;
    cudaGetSymbolAddress((void**)&perm_ptr, g_perm);

    cudaFuncSetAttribute(dec_kernel, cudaFuncAttributeMaxDynamicSharedMemorySize, 204288);
    cudaFuncSetAttribute(mma_gemm_gi, cudaFuncAttributeMaxDynamicSharedMemorySize, MMA_SMEM);
    cudaFuncSetAttribute(mma_gemm_out, cudaFuncAttributeMaxDynamicSharedMemorySize, MMA_SMEM);

    // 1. Fused prep: weight splits + fold + permutations
    prep_kernel<<<417, 256>>>(enc_Wih, out_W, dec_Wih, out_b, dec_bih, perm_ptr);
    // 2. Tensor-core gi GEMM (split-bf16, M-tile 64, 2 CTAs/SM)
    mma_gemm_gi<<<dim3(3, 2048), 256, MMA_SMEM>>>(input, enc_bih);
    // 3. Encoder recurrence (fast gates)
    enc_kernel<<<128, 384>>>(enc_Whh, enc_bhh);
    // 4. Decoder recurrence (fast gates, writes bf16 h split directly)
    dec_kernel<<<128, 384, 204288>>>(dec_Whh, dec_bhh);
    // 5. Tensor-core out GEMM (M-tile 64)
    mma_gemm_out<<<2048, 256, MMA_SMEM>>>(out_b, out);
    // 6. Epilogue (shuffle reductions)
    epiA<<<256, 256>>>(input, protos, lnz_w, lnz_b, lnp_w, lnp_b, lna_w, lna_b,
                       beta, est1_W, est1_b, est2_W, est2_b, out);
    // 7. dis_perm gather
    epiB<<<256, 256>>>(out, perm_ptr);
}